// round 6
// baseline (speedup 1.0000x reference)
#include <cuda_runtime.h>
#include <cuda_bf16.h>
#include <math.h>

// Problem constants (match reference_code)
#define NN 50000
#define EE 400000
#define BB 50

// ---------------- scratch (static device allocations: allowed) ----------------
__device__ __align__(16) float g_bufA[(size_t)NN * 512];
__device__ __align__(16) float g_bufB[(size_t)NN * 512];
__device__ __align__(16) float g_dinv[NN];    // deg^-1/2
__device__ __align__(16) float g_self[NN];    // 1/deg
__device__ __align__(16) float g_ew[EE];      // per-CSR-slot edge weight
__device__ int   g_degi[NN];                  // int degree (no self loop)
__device__ int   g_rowptr[NN + 1];            // CSR row pointers (by dst)
__device__ int   g_cursor[NN];                // fill cursors
__device__ int   g_esrc[EE];                  // CSR column (src node) per slot
__device__ int   g_is64;                      // index dtype flag

__device__ __forceinline__ float* selbuf(int w) { return (w == 0) ? g_bufA : g_bufB; }

__device__ __forceinline__ int ld_idx(const void* p, long long i) {
    if (g_is64) return (int)((const long long*)p)[i];
    return ((const int*)p)[i];
}

// ---------------- dtype detection ----------------
__global__ void detect_kernel(const int* __restrict__ ei32) {
    if (threadIdx.x == 0 && blockIdx.x == 0) {
        int all0 = 1;
        for (int i = 1; i < 4096; i += 2) {
            if (ei32[i] != 0) { all0 = 0; break; }
        }
        g_is64 = all0;
    }
}

// ---------------- CSR build ----------------
__global__ void zero_degi_kernel(int N) {
    int t = blockIdx.x * blockDim.x + threadIdx.x;
    if (t < N) g_degi[t] = 0;
}

__global__ void deg_accum_kernel(const void* __restrict__ ei, int E) {
    int t = blockIdx.x * blockDim.x + threadIdx.x;
    if (t < E) atomicAdd(&g_degi[ld_idx(ei, (long long)E + t)], 1);  // dst row
}

// Single-block scan: thread t serially owns a contiguous chunk; block-scan of
// per-thread totals via warp shuffles; second serial pass writes outputs.
__global__ void scan_kernel(int N) {
    const int T = 1024;
    __shared__ int warp_tot[32];
    int tid  = threadIdx.x;
    int lane = tid & 31, wid = tid >> 5;
    int chunk = (N + T - 1) / T;
    int lo = tid * chunk;
    int hi = min(lo + chunk, N);

    int sum = 0;
    for (int i = lo; i < hi; i++) sum += g_degi[i];

    // inclusive warp scan
    int incl = sum;
#pragma unroll
    for (int off = 1; off < 32; off <<= 1) {
        int v = __shfl_up_sync(0xffffffffu, incl, off);
        if (lane >= off) incl += v;
    }
    if (lane == 31) warp_tot[wid] = incl;
    __syncthreads();
    if (wid == 0) {
        int w = (lane < 32) ? warp_tot[lane] : 0;
#pragma unroll
        for (int off = 1; off < 32; off <<= 1) {
            int v = __shfl_up_sync(0xffffffffu, w, off);
            if (lane >= off) w += v;
        }
        warp_tot[lane] = w;   // inclusive over warps
    }
    __syncthreads();
    int excl = incl - sum + (wid > 0 ? warp_tot[wid - 1] : 0);

    for (int i = lo; i < hi; i++) {
        int v = g_degi[i];
        g_rowptr[i] = excl;
        g_cursor[i] = excl;
        float d  = (float)v + 1.0f;
        float di = rsqrtf(d);
        g_dinv[i] = di;
        g_self[i] = di * di;
        excl += v;
    }
    if (tid == T - 1) g_rowptr[N] = excl;  // trailing threads carry full prefix
}

__global__ void fill_kernel(const void* __restrict__ ei, int E) {
    int e = blockIdx.x * blockDim.x + threadIdx.x;
    if (e >= E) return;
    int s = ld_idx(ei, e);
    int d = ld_idx(ei, (long long)E + e);
    int p = atomicAdd(&g_cursor[d], 1);
    g_esrc[p] = s;
    g_ew[p]   = g_dinv[s] * g_dinv[d];
}

// ---------------- layer 1 matmul (32 -> 8) ----------------
__global__ void mm1_kernel(const float* __restrict__ x,
                           const float* __restrict__ W, int N) {
    __shared__ float Ws[32 * 8];
    for (int i = threadIdx.x; i < 32 * 8; i += blockDim.x) Ws[i] = W[i];
    __syncthreads();
    int t = blockIdx.x * blockDim.x + threadIdx.x;
    int n = t >> 3, c = t & 7;
    if (n >= N) return;
    float acc = 0.0f;
    const float* xr = x + (size_t)n * 32;
#pragma unroll
    for (int k = 0; k < 32; k++) acc = fmaf(xr[k], Ws[k * 8 + c], acc);
    g_bufA[(size_t)n * 8 + c] = acc;
}

// ---------------- CSR gather aggregation ----------------
template <int D4, int BIAS>
__global__ void gather_agg_kernel(int inW, int outW,
                                  const float* __restrict__ bias, int N) {
    int t = blockIdx.x * blockDim.x + threadIdx.x;
    int n = t / D4, c4 = t % D4;
    if (n >= N) return;
    const float4* in4  = (const float4*)selbuf(inW);
    float4*       out4 = (float4*)selbuf(outW);

    float4 b = make_float4(0.f, 0.f, 0.f, 0.f);
    if (BIAS) b = ((const float4*)bias)[c4];

    float4 acc = in4[(size_t)n * D4 + c4];
    if (BIAS) {
        acc.x = fmaxf(acc.x + b.x, 0.f);
        acc.y = fmaxf(acc.y + b.y, 0.f);
        acc.z = fmaxf(acc.z + b.z, 0.f);
        acc.w = fmaxf(acc.w + b.w, 0.f);
    }
    float sn = g_self[n];
    acc.x *= sn; acc.y *= sn; acc.z *= sn; acc.w *= sn;

    int p0 = g_rowptr[n], p1 = g_rowptr[n + 1];
    for (int p = p0; p < p1; p++) {
        int   s = g_esrc[p];
        float w = g_ew[p];
        float4 v = in4[(size_t)s * D4 + c4];
        if (BIAS) {
            v.x = fmaxf(v.x + b.x, 0.f);
            v.y = fmaxf(v.y + b.y, 0.f);
            v.z = fmaxf(v.z + b.z, 0.f);
            v.w = fmaxf(v.w + b.w, 0.f);
        }
        acc.x = fmaf(v.x, w, acc.x);
        acc.y = fmaf(v.y, w, acc.y);
        acc.z = fmaf(v.z, w, acc.z);
        acc.w = fmaf(v.w, w, acc.w);
    }
    out4[(size_t)n * D4 + c4] = acc;
}

// ---------------- small matmul (K,OUT small): C = relu(A@W + b) ----------------
template <int K, int OUT>
__global__ void mm_small_kernel(int inW, int outW,
                                const float* __restrict__ W,
                                const float* __restrict__ bias, int N) {
    __shared__ float Ws[K * OUT];
    __shared__ float bs[OUT];
    for (int i = threadIdx.x; i < K * OUT; i += blockDim.x) Ws[i] = W[i];
    for (int i = threadIdx.x; i < OUT; i += blockDim.x) bs[i] = bias[i];
    __syncthreads();
    const float* A = selbuf(inW);
    float*       C = selbuf(outW);
    int t = blockIdx.x * blockDim.x + threadIdx.x;
    int n = t / OUT, c = t % OUT;
    if (n >= N) return;
    const float* ar = A + (size_t)n * K;
    float acc = 0.0f;
#pragma unroll
    for (int k = 0; k < K; k++) acc = fmaf(ar[k], Ws[k * OUT + c], acc);
    C[(size_t)n * OUT + c] = fmaxf(acc + bs[c], 0.0f);
}

// ---------------- big tiled SGEMM, double-buffered, f32x2 packed FMA ----------
// C[N,OUT] = relu(A[N,K]@W[K,OUT] + b). BM=BN=128, BK=16, TM=8, TN=8 (4 f32x2).
__global__ __launch_bounds__(256, 2)
void sgemm_bias_relu_kernel(int inW, int outW,
                            const float* __restrict__ W,
                            const float* __restrict__ bias,
                            int N, int K, int OUT) {
    constexpr int BM = 128, BN = 128, BK = 16, TM = 8, TN = 8;
    __shared__ float As[2][BK][BM];
    __shared__ float Bs[2][BK][BN];

    const float* A = selbuf(inW);
    float*       C = selbuf(outW);

    const int block_row = blockIdx.x * BM;
    const int block_col = blockIdx.y * BN;
    const int tid  = threadIdx.x;
    const int tcol = tid % (BN / TN);
    const int trow = tid / (BN / TN);

    // acc as packed f32x2 pairs along N: acc2[i][j] = (c[i][2j], c[i][2j+1])
    unsigned long long acc2[TM][TN / 2];
#pragma unroll
    for (int i = 0; i < TM; i++)
#pragma unroll
        for (int j = 0; j < TN / 2; j++) acc2[i][j] = 0ull;  // (0.f, 0.f)

    const int aRow  = tid / (BK / 4);          // 0..63
    const int aCol4 = (tid % (BK / 4)) * 4;    // 0,4,8,12
    const int wRow  = tid / (BN / 4);          // 0..7
    const int wCol4 = (tid % (BN / 4)) * 4;    // 0..124

    auto load_tile = [&](int buf, int k0) {
#pragma unroll
        for (int i = 0; i < BM; i += 64) {
            int r    = i + aRow;
            int grow = block_row + r;
            float4 v = make_float4(0.f, 0.f, 0.f, 0.f);
            if (grow < N) v = *(const float4*)&A[(size_t)grow * K + k0 + aCol4];
            As[buf][aCol4 + 0][r] = v.x;
            As[buf][aCol4 + 1][r] = v.y;
            As[buf][aCol4 + 2][r] = v.z;
            As[buf][aCol4 + 3][r] = v.w;
        }
#pragma unroll
        for (int i = 0; i < BK; i += 8) {
            int r = i + wRow;
            float4 v = *(const float4*)&W[(size_t)(k0 + r) * OUT + block_col + wCol4];
            *(float4*)&Bs[buf][r][wCol4] = v;
        }
    };

    load_tile(0, 0);
    __syncthreads();

    const int ntiles = K / BK;
    for (int ti = 0; ti < ntiles; ti++) {
        int cur = ti & 1;
        if (ti + 1 < ntiles) load_tile(cur ^ 1, (ti + 1) * BK);
#pragma unroll
        for (int k = 0; k < BK; k++) {
            // regN pairs straight from smem (32B-aligned), no packing needed
            ulonglong2 nA = *(const ulonglong2*)&Bs[cur][k][tcol * TN];
            ulonglong2 nB = *(const ulonglong2*)&Bs[cur][k][tcol * TN + 4];
            unsigned long long n2[4] = {nA.x, nA.y, nB.x, nB.y};
            const float* asrow = &As[cur][k][trow * TM];
            float4 mA = *(const float4*)&asrow[0];
            float4 mB = *(const float4*)&asrow[4];
            float regM[TM] = {mA.x, mA.y, mA.z, mA.w, mB.x, mB.y, mB.z, mB.w};
#pragma unroll
            for (int i = 0; i < TM; i++) {
                unsigned long long m2;
                asm("mov.b64 %0, {%1, %1};" : "=l"(m2) : "f"(regM[i]));
#pragma unroll
                for (int j = 0; j < TN / 2; j++) {
                    asm("fma.rn.f32x2 %0, %1, %2, %0;"
                        : "+l"(acc2[i][j]) : "l"(m2), "l"(n2[j]));
                }
            }
        }
        __syncthreads();
    }

#pragma unroll
    for (int i = 0; i < TM; i++) {
        int grow = block_row + trow * TM + i;
        if (grow >= N) continue;
#pragma unroll
        for (int j = 0; j < TN / 2; j += 2) {
            int gcol = block_col + tcol * TN + j * 2;
            float lo0, hi0, lo1, hi1;
            asm("mov.b64 {%0, %1}, %2;" : "=f"(lo0), "=f"(hi0) : "l"(acc2[i][j]));
            asm("mov.b64 {%0, %1}, %2;" : "=f"(lo1), "=f"(hi1) : "l"(acc2[i][j + 1]));
            float4 o;
            o.x = fmaxf(lo0 + bias[gcol + 0], 0.f);
            o.y = fmaxf(hi0 + bias[gcol + 1], 0.f);
            o.z = fmaxf(lo1 + bias[gcol + 2], 0.f);
            o.w = fmaxf(hi1 + bias[gcol + 3], 0.f);
            *(float4*)&C[(size_t)grow * OUT + gcol] = o;
        }
    }
}

// ---------------- mean pool over sorted batch ids ----------------
__device__ __forceinline__ int lower_bound_idx(const void* a, int n, int v) {
    int lo = 0, hi = n;
    while (lo < hi) {
        int m = (lo + hi) >> 1;
        if (ld_idx(a, m) < v) lo = m + 1; else hi = m;
    }
    return lo;
}

__global__ void pool_kernel(int inW,
                            const void* __restrict__ batch,
                            float* __restrict__ out, int N, int B) {
    const float* x = selbuf(inW);
    int b = blockIdx.x;
    int cbase = blockIdx.y * 128;
    __shared__ int s_lo, s_hi;
    if (threadIdx.x == 0) {
        s_lo = lower_bound_idx(batch, N, b);
        s_hi = lower_bound_idx(batch, N, b + 1);
    }
    __syncthreads();
    int lo = s_lo, hi = s_hi;
    float inv = 1.0f / fmaxf((float)(hi - lo), 1.0f);
    int c = cbase + threadIdx.x;
    float s = 0.0f;
    for (int n = lo; n < hi; n++) s += x[(size_t)n * 512 + c];
    out[(size_t)b * 512 + c] = s * inv;
}

// ---------------- launch ----------------
static inline unsigned gr(long long n, int b) { return (unsigned)((n + b - 1) / b); }

extern "C" void kernel_launch(void* const* d_in, const int* in_sizes, int n_in,
                              void* d_out, int out_size) {
    const float* x     = (const float*)d_in[0];
    const void*  ei    = d_in[1];
    const void*  batch = d_in[2];
    const float *W1 = (const float*)d_in[3],  *b1 = (const float*)d_in[4];
    const float *W2 = (const float*)d_in[5],  *b2 = (const float*)d_in[6];
    const float *W3 = (const float*)d_in[7],  *b3 = (const float*)d_in[8];
    const float *W4 = (const float*)d_in[9],  *b4 = (const float*)d_in[10];
    const float *W5 = (const float*)d_in[11], *b5 = (const float*)d_in[12];

    const int N = in_sizes[0] / 32;
    const int E = in_sizes[1] / 2;
    const int B = out_size / 512;

    const int TB = 256;
    const int A = 0, Bb = 1;   // buffer selectors

    // index dtype detection + CSR build + norms
    detect_kernel<<<1, 32>>>((const int*)ei);
    zero_degi_kernel<<<gr(N, TB), TB>>>(N);
    deg_accum_kernel<<<gr(E, TB), TB>>>(ei, E);
    scan_kernel<<<1, 1024>>>(N);
    fill_kernel<<<gr(E, TB), TB>>>(ei, E);

    // Layer 1 (32 -> 8): matmul into bufA, then CSR-gather aggregate (dim 8).
    mm1_kernel<<<gr((long long)N * 8, TB), TB>>>(x, W1, N);
    gather_agg_kernel<2, 0><<<gr((long long)N * 2, TB), TB>>>(A, Bb, nullptr, N);

    // Layer 2 (8 -> 16): aggregate relu(bufB + b1) on dim 8, then matmul.
    gather_agg_kernel<2, 1><<<gr((long long)N * 2, TB), TB>>>(Bb, A, b1, N);
    mm_small_kernel<8, 16><<<gr((long long)N * 16, TB), TB>>>(A, Bb, W2, b2, N);

    // Layer 3 (16 -> 64): aggregate on dim 16.
    gather_agg_kernel<4, 0><<<gr((long long)N * 4, TB), TB>>>(Bb, A, nullptr, N);
    mm_small_kernel<16, 64><<<gr((long long)N * 64, TB), TB>>>(A, Bb, W3, b3, N);

    // Layer 4 (64 -> 256): aggregate on dim 64.
    gather_agg_kernel<16, 0><<<gr((long long)N * 16, TB), TB>>>(Bb, A, nullptr, N);
    {
        dim3 grid(gr(N, 128), 256 / 128);
        sgemm_bias_relu_kernel<<<grid, 256>>>(A, Bb, W4, b4, N, 64, 256);
    }

    // Layer 5 (256 -> 512): aggregate on dim 256.
    gather_agg_kernel<64, 0><<<gr((long long)N * 64, TB), TB>>>(Bb, A, nullptr, N);
    {
        dim3 grid(gr(N, 128), 512 / 128);
        sgemm_bias_relu_kernel<<<grid, 256>>>(A, Bb, W5, b5, N, 256, 512);
    }

    // Global mean pool
    dim3 pgrid(B, 4);
    pool_kernel<<<pgrid, 128>>>(Bb, batch, (float*)d_out, N, B);
}

// round 7
// speedup vs baseline: 1.2019x; 1.2019x over previous
#include <cuda_runtime.h>
#include <cuda_bf16.h>
#include <math.h>

// Problem constants (match reference_code)
#define NN 50000
#define EE 400000
#define BB 50

// ---------------- scratch (static device allocations: allowed) ----------------
__device__ __align__(16) float g_bufA[(size_t)NN * 512];
__device__ __align__(16) float g_bufB[(size_t)NN * 512];
__device__ __align__(16) float g_dinv[NN];    // deg^-1/2
__device__ __align__(16) float g_self[NN];    // 1/deg
__device__ __align__(16) float g_ew[EE];      // per-CSR-slot edge weight
__device__ int   g_degi[NN];                  // int degree (no self loop)
__device__ int   g_rowptr[NN + 1];            // CSR row pointers (by dst)
__device__ int   g_cursor[NN];                // fill cursors
__device__ int   g_esrc[EE];                  // CSR column (src node) per slot
__device__ int   g_bsum[64];                  // per-block scan totals
__device__ int   g_is64;                      // index dtype flag

__device__ __forceinline__ float* selbuf(int w) { return (w == 0) ? g_bufA : g_bufB; }

__device__ __forceinline__ int ld_idx(const void* p, long long i) {
    if (g_is64) return (int)((const long long*)p)[i];
    return ((const int*)p)[i];
}

// ---------------- dtype detection ----------------
__global__ void detect_kernel(const int* __restrict__ ei32) {
    if (threadIdx.x == 0 && blockIdx.x == 0) {
        int all0 = 1;
        for (int i = 1; i < 4096; i += 2) {
            if (ei32[i] != 0) { all0 = 0; break; }
        }
        g_is64 = all0;
    }
}

// ---------------- CSR build ----------------
__global__ void zero_degi_kernel(int N) {
    int t = blockIdx.x * blockDim.x + threadIdx.x;
    if (t < N) g_degi[t] = 0;
}

__global__ void deg_accum_kernel(const void* __restrict__ ei, int E) {
    int t = blockIdx.x * blockDim.x + threadIdx.x;
    if (t < E) atomicAdd(&g_degi[ld_idx(ei, (long long)E + t)], 1);  // dst row
}

// 3-phase scan. Phase 1: per-block inclusive scan (coalesced), totals -> g_bsum.
__global__ void scan_phase1(int N) {
    __shared__ int warp_tot[32];
    int i    = blockIdx.x * 1024 + threadIdx.x;
    int lane = threadIdx.x & 31, wid = threadIdx.x >> 5;
    int v = (i < N) ? g_degi[i] : 0;

    int incl = v;
#pragma unroll
    for (int off = 1; off < 32; off <<= 1) {
        int u = __shfl_up_sync(0xffffffffu, incl, off);
        if (lane >= off) incl += u;
    }
    if (lane == 31) warp_tot[wid] = incl;
    __syncthreads();
    if (wid == 0) {
        int w = warp_tot[lane];
#pragma unroll
        for (int off = 1; off < 32; off <<= 1) {
            int u = __shfl_up_sync(0xffffffffu, w, off);
            if (lane >= off) w += u;
        }
        warp_tot[lane] = w;
    }
    __syncthreads();
    if (wid > 0) incl += warp_tot[wid - 1];
    if (i < N) g_rowptr[i] = incl;               // temp: block-local inclusive
    if (threadIdx.x == 1023) g_bsum[blockIdx.x] = incl;
}

// Phase 2: exclusive scan of up to 64 block totals (one 64-thread block).
__global__ void scan_phase2(int nb) {
    __shared__ int w0tot;
    int t = threadIdx.x;                          // 0..63
    int lane = t & 31, wid = t >> 5;
    int v = (t < nb) ? g_bsum[t] : 0;
    int incl = v;
#pragma unroll
    for (int off = 1; off < 32; off <<= 1) {
        int u = __shfl_up_sync(0xffffffffu, incl, off);
        if (lane >= off) incl += u;
    }
    if (t == 31) w0tot = incl;
    __syncthreads();
    int excl = incl - v + (wid == 1 ? w0tot : 0);
    if (t < nb) g_bsum[t] = excl;
}

// Phase 3: finalize rowptr/cursor/dinv/self.
__global__ void scan_phase3(int N) {
    int i = blockIdx.x * 1024 + threadIdx.x;
    if (i >= N) return;
    int v    = g_degi[i];
    int incl = g_rowptr[i] + g_bsum[blockIdx.x];
    int excl = incl - v;
    g_rowptr[i] = excl;
    g_cursor[i] = excl;
    float d  = (float)v + 1.0f;
    float di = rsqrtf(d);
    g_dinv[i] = di;
    g_self[i] = di * di;
    if (i == N - 1) g_rowptr[N] = incl;
}

__global__ void fill_kernel(const void* __restrict__ ei, int E) {
    int e = blockIdx.x * blockDim.x + threadIdx.x;
    if (e >= E) return;
    int s = ld_idx(ei, e);
    int d = ld_idx(ei, (long long)E + e);
    int p = atomicAdd(&g_cursor[d], 1);
    g_esrc[p] = s;
    g_ew[p]   = g_dinv[s] * g_dinv[d];
}

// ---------------- layer 1 matmul (32 -> 8) ----------------
__global__ void mm1_kernel(const float* __restrict__ x,
                           const float* __restrict__ W, int N) {
    __shared__ float Ws[32 * 8];
    for (int i = threadIdx.x; i < 32 * 8; i += blockDim.x) Ws[i] = W[i];
    __syncthreads();
    int t = blockIdx.x * blockDim.x + threadIdx.x;
    int n = t >> 3, c = t & 7;
    if (n >= N) return;
    float acc = 0.0f;
    const float* xr = x + (size_t)n * 32;
#pragma unroll
    for (int k = 0; k < 32; k++) acc = fmaf(xr[k], Ws[k * 8 + c], acc);
    g_bufA[(size_t)n * 8 + c] = acc;
}

// ---------------- CSR gather aggregation ----------------
template <int D4, int BIAS>
__global__ void gather_agg_kernel(int inW, int outW,
                                  const float* __restrict__ bias, int N) {
    int t = blockIdx.x * blockDim.x + threadIdx.x;
    int n = t / D4, c4 = t % D4;
    if (n >= N) return;
    const float4* in4  = (const float4*)selbuf(inW);
    float4*       out4 = (float4*)selbuf(outW);

    float4 b = make_float4(0.f, 0.f, 0.f, 0.f);
    if (BIAS) b = ((const float4*)bias)[c4];

    float4 acc = in4[(size_t)n * D4 + c4];
    if (BIAS) {
        acc.x = fmaxf(acc.x + b.x, 0.f);
        acc.y = fmaxf(acc.y + b.y, 0.f);
        acc.z = fmaxf(acc.z + b.z, 0.f);
        acc.w = fmaxf(acc.w + b.w, 0.f);
    }
    float sn = g_self[n];
    acc.x *= sn; acc.y *= sn; acc.z *= sn; acc.w *= sn;

    int p0 = g_rowptr[n], p1 = g_rowptr[n + 1];
    for (int p = p0; p < p1; p++) {
        int   s = g_esrc[p];
        float w = g_ew[p];
        float4 v = in4[(size_t)s * D4 + c4];
        if (BIAS) {
            v.x = fmaxf(v.x + b.x, 0.f);
            v.y = fmaxf(v.y + b.y, 0.f);
            v.z = fmaxf(v.z + b.z, 0.f);
            v.w = fmaxf(v.w + b.w, 0.f);
        }
        acc.x = fmaf(v.x, w, acc.x);
        acc.y = fmaf(v.y, w, acc.y);
        acc.z = fmaf(v.z, w, acc.z);
        acc.w = fmaf(v.w, w, acc.w);
    }
    out4[(size_t)n * D4 + c4] = acc;
}

// ---------------- small matmul (K,OUT small): C = relu(A@W + b) ----------------
template <int K, int OUT>
__global__ void mm_small_kernel(int inW, int outW,
                                const float* __restrict__ W,
                                const float* __restrict__ bias, int N) {
    __shared__ float Ws[K * OUT];
    __shared__ float bs[OUT];
    for (int i = threadIdx.x; i < K * OUT; i += blockDim.x) Ws[i] = W[i];
    for (int i = threadIdx.x; i < OUT; i += blockDim.x) bs[i] = bias[i];
    __syncthreads();
    const float* A = selbuf(inW);
    float*       C = selbuf(outW);
    int t = blockIdx.x * blockDim.x + threadIdx.x;
    int n = t / OUT, c = t % OUT;
    if (n >= N) return;
    const float* ar = A + (size_t)n * K;
    float acc = 0.0f;
#pragma unroll
    for (int k = 0; k < K; k++) acc = fmaf(ar[k], Ws[k * OUT + c], acc);
    C[(size_t)n * OUT + c] = fmaxf(acc + bs[c], 0.0f);
}

// ---------------- big tiled SGEMM, double-buffered (R5 proven version) --------
__global__ __launch_bounds__(256, 2)
void sgemm_bias_relu_kernel(int inW, int outW,
                            const float* __restrict__ W,
                            const float* __restrict__ bias,
                            int N, int K, int OUT) {
    constexpr int BM = 128, BN = 128, BK = 16, TM = 8, TN = 8;
    __shared__ float As[2][BK][BM];
    __shared__ float Bs[2][BK][BN];

    const float* A = selbuf(inW);
    float*       C = selbuf(outW);

    const int block_row = blockIdx.x * BM;
    const int block_col = blockIdx.y * BN;
    const int tid  = threadIdx.x;
    const int tcol = tid % (BN / TN);
    const int trow = tid / (BN / TN);

    float acc[TM][TN] = {};

    const int aRow  = tid / (BK / 4);          // 0..63
    const int aCol4 = (tid % (BK / 4)) * 4;    // 0,4,8,12
    const int wRow  = tid / (BN / 4);          // 0..7
    const int wCol4 = (tid % (BN / 4)) * 4;    // 0..124

    auto load_tile = [&](int buf, int k0) {
#pragma unroll
        for (int i = 0; i < BM; i += 64) {
            int r    = i + aRow;
            int grow = block_row + r;
            float4 v = make_float4(0.f, 0.f, 0.f, 0.f);
            if (grow < N) v = *(const float4*)&A[(size_t)grow * K + k0 + aCol4];
            As[buf][aCol4 + 0][r] = v.x;
            As[buf][aCol4 + 1][r] = v.y;
            As[buf][aCol4 + 2][r] = v.z;
            As[buf][aCol4 + 3][r] = v.w;
        }
#pragma unroll
        for (int i = 0; i < BK; i += 8) {
            int r = i + wRow;
            float4 v = *(const float4*)&W[(size_t)(k0 + r) * OUT + block_col + wCol4];
            *(float4*)&Bs[buf][r][wCol4] = v;
        }
    };

    load_tile(0, 0);
    __syncthreads();

    const int ntiles = K / BK;
    for (int ti = 0; ti < ntiles; ti++) {
        int cur = ti & 1;
        if (ti + 1 < ntiles) load_tile(cur ^ 1, (ti + 1) * BK);
#pragma unroll
        for (int k = 0; k < BK; k++) {
            float regM[TM], regN[TN];
#pragma unroll
            for (int i = 0; i < TM; i++) regM[i] = As[cur][k][trow * TM + i];
#pragma unroll
            for (int j = 0; j < TN; j++) regN[j] = Bs[cur][k][tcol * TN + j];
#pragma unroll
            for (int i = 0; i < TM; i++)
#pragma unroll
                for (int j = 0; j < TN; j++)
                    acc[i][j] = fmaf(regM[i], regN[j], acc[i][j]);
        }
        __syncthreads();
    }

#pragma unroll
    for (int i = 0; i < TM; i++) {
        int grow = block_row + trow * TM + i;
        if (grow >= N) continue;
#pragma unroll
        for (int j = 0; j < TN; j += 4) {
            int gcol = block_col + tcol * TN + j;
            float4 o;
            o.x = fmaxf(acc[i][j + 0] + bias[gcol + 0], 0.f);
            o.y = fmaxf(acc[i][j + 1] + bias[gcol + 1], 0.f);
            o.z = fmaxf(acc[i][j + 2] + bias[gcol + 2], 0.f);
            o.w = fmaxf(acc[i][j + 3] + bias[gcol + 3], 0.f);
            *(float4*)&C[(size_t)grow * OUT + gcol] = o;
        }
    }
}

// ---------------- mean pool over sorted batch ids ----------------
__device__ __forceinline__ int lower_bound_idx(const void* a, int n, int v) {
    int lo = 0, hi = n;
    while (lo < hi) {
        int m = (lo + hi) >> 1;
        if (ld_idx(a, m) < v) lo = m + 1; else hi = m;
    }
    return lo;
}

__global__ void pool_kernel(int inW,
                            const void* __restrict__ batch,
                            float* __restrict__ out, int N, int B) {
    const float* x = selbuf(inW);
    int b = blockIdx.x;
    int cbase = blockIdx.y * 128;
    __shared__ int s_lo, s_hi;
    if (threadIdx.x == 0) {
        s_lo = lower_bound_idx(batch, N, b);
        s_hi = lower_bound_idx(batch, N, b + 1);
    }
    __syncthreads();
    int lo = s_lo, hi = s_hi;
    float inv = 1.0f / fmaxf((float)(hi - lo), 1.0f);
    int c = cbase + threadIdx.x;
    float s = 0.0f;
    for (int n = lo; n < hi; n++) s += x[(size_t)n * 512 + c];
    out[(size_t)b * 512 + c] = s * inv;
}

// ---------------- launch ----------------
static inline unsigned gr(long long n, int b) { return (unsigned)((n + b - 1) / b); }

extern "C" void kernel_launch(void* const* d_in, const int* in_sizes, int n_in,
                              void* d_out, int out_size) {
    const float* x     = (const float*)d_in[0];
    const void*  ei    = d_in[1];
    const void*  batch = d_in[2];
    const float *W1 = (const float*)d_in[3],  *b1 = (const float*)d_in[4];
    const float *W2 = (const float*)d_in[5],  *b2 = (const float*)d_in[6];
    const float *W3 = (const float*)d_in[7],  *b3 = (const float*)d_in[8];
    const float *W4 = (const float*)d_in[9],  *b4 = (const float*)d_in[10];
    const float *W5 = (const float*)d_in[11], *b5 = (const float*)d_in[12];

    const int N = in_sizes[0] / 32;
    const int E = in_sizes[1] / 2;
    const int B = out_size / 512;

    const int TB = 256;
    const int A = 0, Bb = 1;   // buffer selectors
    const int nb = (N + 1023) / 1024;

    // index dtype detection + CSR build + norms
    detect_kernel<<<1, 32>>>((const int*)ei);
    zero_degi_kernel<<<gr(N, TB), TB>>>(N);
    deg_accum_kernel<<<gr(E, TB), TB>>>(ei, E);
    scan_phase1<<<nb, 1024>>>(N);
    scan_phase2<<<1, 64>>>(nb);
    scan_phase3<<<nb, 1024>>>(N);
    fill_kernel<<<gr(E, TB), TB>>>(ei, E);

    // Layer 1 (32 -> 8): matmul into bufA, then CSR-gather aggregate (dim 8).
    mm1_kernel<<<gr((long long)N * 8, TB), TB>>>(x, W1, N);
    gather_agg_kernel<2, 0><<<gr((long long)N * 2, TB), TB>>>(A, Bb, nullptr, N);

    // Layer 2 (8 -> 16): aggregate relu(bufB + b1) on dim 8, then matmul.
    gather_agg_kernel<2, 1><<<gr((long long)N * 2, TB), TB>>>(Bb, A, b1, N);
    mm_small_kernel<8, 16><<<gr((long long)N * 16, TB), TB>>>(A, Bb, W2, b2, N);

    // Layer 3 (16 -> 64): aggregate on dim 16.
    gather_agg_kernel<4, 0><<<gr((long long)N * 4, TB), TB>>>(Bb, A, nullptr, N);
    mm_small_kernel<16, 64><<<gr((long long)N * 64, TB), TB>>>(A, Bb, W3, b3, N);

    // Layer 4 (64 -> 256): aggregate on dim 64.
    gather_agg_kernel<16, 0><<<gr((long long)N * 16, TB), TB>>>(Bb, A, nullptr, N);
    {
        dim3 grid(gr(N, 128), 256 / 128);
        sgemm_bias_relu_kernel<<<grid, 256>>>(A, Bb, W4, b4, N, 64, 256);
    }

    // Layer 5 (256 -> 512): aggregate on dim 256.
    gather_agg_kernel<64, 0><<<gr((long long)N * 64, TB), TB>>>(Bb, A, nullptr, N);
    {
        dim3 grid(gr(N, 128), 512 / 128);
        sgemm_bias_relu_kernel<<<grid, 256>>>(A, Bb, W5, b5, N, 256, 512);
    }

    // Global mean pool
    dim3 pgrid(B, 4);
    pool_kernel<<<pgrid, 128>>>(Bb, batch, (float*)d_out, N, B);
}

// round 8
// speedup vs baseline: 1.9493x; 1.6218x over previous
#include <cuda_runtime.h>
#include <cuda_bf16.h>
#include <math.h>

// Problem constants (match reference_code)
#define NN 50000
#define EE 400000
#define BB 50

// ---------------- scratch (static device allocations: allowed) ----------------
__device__ __align__(16) float g_bufA[(size_t)NN * 512];
__device__ __align__(16) float g_bufB[(size_t)NN * 512];
__device__ __align__(16) float g_dinv[NN];    // deg^-1/2
__device__ __align__(16) float g_self[NN];    // 1/deg
__device__ __align__(16) float g_ew[EE];      // per-CSR-slot edge weight
__device__ int   g_degi[NN];                  // int degree (no self loop)
__device__ int   g_rowptr[NN + 1];            // CSR row pointers (by dst)
__device__ int   g_cursor[NN];                // fill cursors
__device__ int   g_esrc[EE];                  // CSR column (src node) per slot
__device__ int   g_bsum[64];                  // per-block scan totals
__device__ int   g_is64;                      // index dtype flag

__device__ __forceinline__ float* selbuf(int w) { return (w == 0) ? g_bufA : g_bufB; }

__device__ __forceinline__ int ld_idx(const void* p, long long i) {
    if (g_is64) return (int)((const long long*)p)[i];
    return ((const int*)p)[i];
}

__device__ __forceinline__ unsigned f2tf32(float x) {
    unsigned u;
    asm("cvt.rna.tf32.f32 %0, %1;" : "=r"(u) : "f"(x));
    return u;
}

// ---------------- dtype detection ----------------
__global__ void detect_kernel(const int* __restrict__ ei32) {
    if (threadIdx.x == 0 && blockIdx.x == 0) {
        int all0 = 1;
        for (int i = 1; i < 4096; i += 2) {
            if (ei32[i] != 0) { all0 = 0; break; }
        }
        g_is64 = all0;
    }
}

// ---------------- CSR build ----------------
__global__ void zero_degi_kernel(int N) {
    int t = blockIdx.x * blockDim.x + threadIdx.x;
    if (t < N) g_degi[t] = 0;
}

__global__ void deg_accum_kernel(const void* __restrict__ ei, int E) {
    int t = blockIdx.x * blockDim.x + threadIdx.x;
    if (t < E) atomicAdd(&g_degi[ld_idx(ei, (long long)E + t)], 1);  // dst row
}

__global__ void scan_phase1(int N) {
    __shared__ int warp_tot[32];
    int i    = blockIdx.x * 1024 + threadIdx.x;
    int lane = threadIdx.x & 31, wid = threadIdx.x >> 5;
    int v = (i < N) ? g_degi[i] : 0;

    int incl = v;
#pragma unroll
    for (int off = 1; off < 32; off <<= 1) {
        int u = __shfl_up_sync(0xffffffffu, incl, off);
        if (lane >= off) incl += u;
    }
    if (lane == 31) warp_tot[wid] = incl;
    __syncthreads();
    if (wid == 0) {
        int w = warp_tot[lane];
#pragma unroll
        for (int off = 1; off < 32; off <<= 1) {
            int u = __shfl_up_sync(0xffffffffu, w, off);
            if (lane >= off) w += u;
        }
        warp_tot[lane] = w;
    }
    __syncthreads();
    if (wid > 0) incl += warp_tot[wid - 1];
    if (i < N) g_rowptr[i] = incl;               // temp: block-local inclusive
    if (threadIdx.x == 1023) g_bsum[blockIdx.x] = incl;
}

__global__ void scan_phase2(int nb) {
    __shared__ int w0tot;
    int t = threadIdx.x;                          // 0..63
    int lane = t & 31, wid = t >> 5;
    int v = (t < nb) ? g_bsum[t] : 0;
    int incl = v;
#pragma unroll
    for (int off = 1; off < 32; off <<= 1) {
        int u = __shfl_up_sync(0xffffffffu, incl, off);
        if (lane >= off) incl += u;
    }
    if (t == 31) w0tot = incl;
    __syncthreads();
    int excl = incl - v + (wid == 1 ? w0tot : 0);
    if (t < nb) g_bsum[t] = excl;
}

__global__ void scan_phase3(int N) {
    int i = blockIdx.x * 1024 + threadIdx.x;
    if (i >= N) return;
    int v    = g_degi[i];
    int incl = g_rowptr[i] + g_bsum[blockIdx.x];
    int excl = incl - v;
    g_rowptr[i] = excl;
    g_cursor[i] = excl;
    float d  = (float)v + 1.0f;
    float di = rsqrtf(d);
    g_dinv[i] = di;
    g_self[i] = di * di;
    if (i == N - 1) g_rowptr[N] = incl;
}

__global__ void fill_kernel(const void* __restrict__ ei, int E) {
    int e = blockIdx.x * blockDim.x + threadIdx.x;
    if (e >= E) return;
    int s = ld_idx(ei, e);
    int d = ld_idx(ei, (long long)E + e);
    int p = atomicAdd(&g_cursor[d], 1);
    g_esrc[p] = s;
    g_ew[p]   = g_dinv[s] * g_dinv[d];
}

// ---------------- layer 1 matmul (32 -> 8) ----------------
__global__ void mm1_kernel(const float* __restrict__ x,
                           const float* __restrict__ W, int N) {
    __shared__ float Ws[32 * 8];
    for (int i = threadIdx.x; i < 32 * 8; i += blockDim.x) Ws[i] = W[i];
    __syncthreads();
    int t = blockIdx.x * blockDim.x + threadIdx.x;
    int n = t >> 3, c = t & 7;
    if (n >= N) return;
    float acc = 0.0f;
    const float* xr = x + (size_t)n * 32;
#pragma unroll
    for (int k = 0; k < 32; k++) acc = fmaf(xr[k], Ws[k * 8 + c], acc);
    g_bufA[(size_t)n * 8 + c] = acc;
}

// ---------------- CSR gather aggregation ----------------
template <int D4, int BIAS>
__global__ void gather_agg_kernel(int inW, int outW,
                                  const float* __restrict__ bias, int N) {
    int t = blockIdx.x * blockDim.x + threadIdx.x;
    int n = t / D4, c4 = t % D4;
    if (n >= N) return;
    const float4* in4  = (const float4*)selbuf(inW);
    float4*       out4 = (float4*)selbuf(outW);

    float4 b = make_float4(0.f, 0.f, 0.f, 0.f);
    if (BIAS) b = ((const float4*)bias)[c4];

    float4 acc = in4[(size_t)n * D4 + c4];
    if (BIAS) {
        acc.x = fmaxf(acc.x + b.x, 0.f);
        acc.y = fmaxf(acc.y + b.y, 0.f);
        acc.z = fmaxf(acc.z + b.z, 0.f);
        acc.w = fmaxf(acc.w + b.w, 0.f);
    }
    float sn = g_self[n];
    acc.x *= sn; acc.y *= sn; acc.z *= sn; acc.w *= sn;

    int p0 = g_rowptr[n], p1 = g_rowptr[n + 1];
    for (int p = p0; p < p1; p++) {
        int   s = g_esrc[p];
        float w = g_ew[p];
        float4 v = in4[(size_t)s * D4 + c4];
        if (BIAS) {
            v.x = fmaxf(v.x + b.x, 0.f);
            v.y = fmaxf(v.y + b.y, 0.f);
            v.z = fmaxf(v.z + b.z, 0.f);
            v.w = fmaxf(v.w + b.w, 0.f);
        }
        acc.x = fmaf(v.x, w, acc.x);
        acc.y = fmaf(v.y, w, acc.y);
        acc.z = fmaf(v.z, w, acc.z);
        acc.w = fmaf(v.w, w, acc.w);
    }
    out4[(size_t)n * D4 + c4] = acc;
}

// ---------------- small matmul (K,OUT small): C = relu(A@W + b) ----------------
template <int K, int OUT>
__global__ void mm_small_kernel(int inW, int outW,
                                const float* __restrict__ W,
                                const float* __restrict__ bias, int N) {
    __shared__ float Ws[K * OUT];
    __shared__ float bs[OUT];
    for (int i = threadIdx.x; i < K * OUT; i += blockDim.x) Ws[i] = W[i];
    for (int i = threadIdx.x; i < OUT; i += blockDim.x) bs[i] = bias[i];
    __syncthreads();
    const float* A = selbuf(inW);
    float*       C = selbuf(outW);
    int t = blockIdx.x * blockDim.x + threadIdx.x;
    int n = t / OUT, c = t % OUT;
    if (n >= N) return;
    const float* ar = A + (size_t)n * K;
    float acc = 0.0f;
#pragma unroll
    for (int k = 0; k < K; k++) acc = fmaf(ar[k], Ws[k * OUT + c], acc);
    C[(size_t)n * OUT + c] = fmaxf(acc + bs[c], 0.0f);
}

// ---------------- TF32 tensor-core GEMM: C = relu(A@W + b) --------------------
// BM=BN=128, BK=16, 256 threads = 8 warps (2 M x 4 N), warp tile 64x32.
// mma.sync.m16n8k8 tf32. A/B staged in smem as tf32 bit patterns, +8 padding
// makes fragment LDS conflict-free (bank = 8*tig + gid, all distinct).
__global__ __launch_bounds__(256, 2)
void tf32_gemm_bias_relu(int inW, int outW,
                         const float* __restrict__ W,
                         const float* __restrict__ bias,
                         int N, int K, int OUT) {
    constexpr int BM = 128, BN = 128, BK = 16;
    __shared__ unsigned As[2][BK][BM + 8];
    __shared__ unsigned Bs[2][BK][BN + 8];

    const float* A = selbuf(inW);
    float*       C = selbuf(outW);

    const int block_row = blockIdx.x * BM;
    const int block_col = blockIdx.y * BN;
    const int tid    = threadIdx.x;
    const int lane   = tid & 31;
    const int warpId = tid >> 5;
    const int warpM  = warpId & 1;    // 0..1  (64 rows each)
    const int warpN  = warpId >> 1;   // 0..3  (32 cols each)
    const int gid    = lane >> 2;     // 0..7
    const int tig    = lane & 3;      // 0..3

    float c[4][4][4];                 // [mTile][nTile][reg]
#pragma unroll
    for (int i = 0; i < 4; i++)
#pragma unroll
        for (int j = 0; j < 4; j++)
#pragma unroll
            for (int r = 0; r < 4; r++) c[i][j][r] = 0.0f;

    const int aRow  = tid >> 2;           // 0..63
    const int aCol4 = (tid & 3) * 4;      // 0,4,8,12
    const int wRow  = tid >> 5;           // 0..7
    const int wCol4 = (tid & 31) * 4;     // 0..124

    auto load_tile = [&](int buf, int k0) {
#pragma unroll
        for (int i = 0; i < BM; i += 64) {
            int r    = i + aRow;
            int grow = block_row + r;
            float4 v = make_float4(0.f, 0.f, 0.f, 0.f);
            if (grow < N) v = *(const float4*)&A[(size_t)grow * K + k0 + aCol4];
            As[buf][aCol4 + 0][r] = f2tf32(v.x);
            As[buf][aCol4 + 1][r] = f2tf32(v.y);
            As[buf][aCol4 + 2][r] = f2tf32(v.z);
            As[buf][aCol4 + 3][r] = f2tf32(v.w);
        }
#pragma unroll
        for (int i = 0; i < BK; i += 8) {
            int r = i + wRow;
            float4 v = *(const float4*)&W[(size_t)(k0 + r) * OUT + block_col + wCol4];
            Bs[buf][r][wCol4 + 0] = f2tf32(v.x);
            Bs[buf][r][wCol4 + 1] = f2tf32(v.y);
            Bs[buf][r][wCol4 + 2] = f2tf32(v.z);
            Bs[buf][r][wCol4 + 3] = f2tf32(v.w);
        }
    };

    load_tile(0, 0);
    __syncthreads();

    const int ntiles = K / BK;
    for (int ti = 0; ti < ntiles; ti++) {
        int cur = ti & 1;
        if (ti + 1 < ntiles) load_tile(cur ^ 1, (ti + 1) * BK);
#pragma unroll
        for (int k8 = 0; k8 < 2; k8++) {
            const int kb = k8 * 8;
            unsigned a[4][4], b[4][2];
#pragma unroll
            for (int mt = 0; mt < 4; mt++) {
                int mb = warpM * 64 + mt * 16;
                a[mt][0] = As[cur][kb + tig][mb + gid];
                a[mt][1] = As[cur][kb + tig][mb + gid + 8];
                a[mt][2] = As[cur][kb + tig + 4][mb + gid];
                a[mt][3] = As[cur][kb + tig + 4][mb + gid + 8];
            }
#pragma unroll
            for (int nt = 0; nt < 4; nt++) {
                int nb = warpN * 32 + nt * 8;
                b[nt][0] = Bs[cur][kb + tig][nb + gid];
                b[nt][1] = Bs[cur][kb + tig + 4][nb + gid];
            }
#pragma unroll
            for (int mt = 0; mt < 4; mt++)
#pragma unroll
                for (int nt = 0; nt < 4; nt++) {
                    asm volatile(
                        "mma.sync.aligned.m16n8k8.row.col.f32.tf32.tf32.f32 "
                        "{%0,%1,%2,%3}, {%4,%5,%6,%7}, {%8,%9}, {%0,%1,%2,%3};"
                        : "+f"(c[mt][nt][0]), "+f"(c[mt][nt][1]),
                          "+f"(c[mt][nt][2]), "+f"(c[mt][nt][3])
                        : "r"(a[mt][0]), "r"(a[mt][1]), "r"(a[mt][2]), "r"(a[mt][3]),
                          "r"(b[nt][0]), "r"(b[nt][1]));
                }
        }
        __syncthreads();
    }

    // Epilogue: c0,c1 -> (row, col..col+1); c2,c3 -> (row+8, col..col+1)
#pragma unroll
    for (int mt = 0; mt < 4; mt++) {
        int row0 = block_row + warpM * 64 + mt * 16 + gid;
#pragma unroll
        for (int nt = 0; nt < 4; nt++) {
            int col = block_col + warpN * 32 + nt * 8 + tig * 2;
            float bx = bias[col], by = bias[col + 1];
            if (row0 < N) {
                float2 o;
                o.x = fmaxf(c[mt][nt][0] + bx, 0.f);
                o.y = fmaxf(c[mt][nt][1] + by, 0.f);
                *(float2*)&C[(size_t)row0 * OUT + col] = o;
            }
            if (row0 + 8 < N) {
                float2 o;
                o.x = fmaxf(c[mt][nt][2] + bx, 0.f);
                o.y = fmaxf(c[mt][nt][3] + by, 0.f);
                *(float2*)&C[(size_t)(row0 + 8) * OUT + col] = o;
            }
        }
    }
}

// ---------------- mean pool over sorted batch ids ----------------
__device__ __forceinline__ int lower_bound_idx(const void* a, int n, int v) {
    int lo = 0, hi = n;
    while (lo < hi) {
        int m = (lo + hi) >> 1;
        if (ld_idx(a, m) < v) lo = m + 1; else hi = m;
    }
    return lo;
}

__global__ void pool_kernel(int inW,
                            const void* __restrict__ batch,
                            float* __restrict__ out, int N, int B) {
    const float* x = selbuf(inW);
    int b = blockIdx.x;
    int cbase = blockIdx.y * 128;
    __shared__ int s_lo, s_hi;
    if (threadIdx.x == 0) {
        s_lo = lower_bound_idx(batch, N, b);
        s_hi = lower_bound_idx(batch, N, b + 1);
    }
    __syncthreads();
    int lo = s_lo, hi = s_hi;
    float inv = 1.0f / fmaxf((float)(hi - lo), 1.0f);
    int c = cbase + threadIdx.x;
    float s = 0.0f;
    for (int n = lo; n < hi; n++) s += x[(size_t)n * 512 + c];
    out[(size_t)b * 512 + c] = s * inv;
}

// ---------------- launch ----------------
static inline unsigned gr(long long n, int b) { return (unsigned)((n + b - 1) / b); }

extern "C" void kernel_launch(void* const* d_in, const int* in_sizes, int n_in,
                              void* d_out, int out_size) {
    const float* x     = (const float*)d_in[0];
    const void*  ei    = d_in[1];
    const void*  batch = d_in[2];
    const float *W1 = (const float*)d_in[3],  *b1 = (const float*)d_in[4];
    const float *W2 = (const float*)d_in[5],  *b2 = (const float*)d_in[6];
    const float *W3 = (const float*)d_in[7],  *b3 = (const float*)d_in[8];
    const float *W4 = (const float*)d_in[9],  *b4 = (const float*)d_in[10];
    const float *W5 = (const float*)d_in[11], *b5 = (const float*)d_in[12];

    const int N = in_sizes[0] / 32;
    const int E = in_sizes[1] / 2;
    const int B = out_size / 512;

    const int TB = 256;
    const int A = 0, Bb = 1;   // buffer selectors
    const int nb = (N + 1023) / 1024;

    // index dtype detection + CSR build + norms
    detect_kernel<<<1, 32>>>((const int*)ei);
    zero_degi_kernel<<<gr(N, TB), TB>>>(N);
    deg_accum_kernel<<<gr(E, TB), TB>>>(ei, E);
    scan_phase1<<<nb, 1024>>>(N);
    scan_phase2<<<1, 64>>>(nb);
    scan_phase3<<<nb, 1024>>>(N);
    fill_kernel<<<gr(E, TB), TB>>>(ei, E);

    // Layer 1 (32 -> 8): matmul into bufA, then CSR-gather aggregate (dim 8).
    mm1_kernel<<<gr((long long)N * 8, TB), TB>>>(x, W1, N);
    gather_agg_kernel<2, 0><<<gr((long long)N * 2, TB), TB>>>(A, Bb, nullptr, N);

    // Layer 2 (8 -> 16): aggregate relu(bufB + b1) on dim 8, then matmul.
    gather_agg_kernel<2, 1><<<gr((long long)N * 2, TB), TB>>>(Bb, A, b1, N);
    mm_small_kernel<8, 16><<<gr((long long)N * 16, TB), TB>>>(A, Bb, W2, b2, N);

    // Layer 3 (16 -> 64): aggregate on dim 16.
    gather_agg_kernel<4, 0><<<gr((long long)N * 4, TB), TB>>>(Bb, A, nullptr, N);
    mm_small_kernel<16, 64><<<gr((long long)N * 64, TB), TB>>>(A, Bb, W3, b3, N);

    // Layer 4 (64 -> 256): aggregate on dim 64, then TF32 GEMM.
    gather_agg_kernel<16, 0><<<gr((long long)N * 16, TB), TB>>>(Bb, A, nullptr, N);
    {
        dim3 grid(gr(N, 128), 256 / 128);
        tf32_gemm_bias_relu<<<grid, 256>>>(A, Bb, W4, b4, N, 64, 256);
    }

    // Layer 5 (256 -> 512): aggregate on dim 256, then TF32 GEMM.
    gather_agg_kernel<64, 0><<<gr((long long)N * 64, TB), TB>>>(Bb, A, nullptr, N);
    {
        dim3 grid(gr(N, 128), 512 / 128);
        tf32_gemm_bias_relu<<<grid, 256>>>(A, Bb, W5, b5, N, 256, 512);
    }

    // Global mean pool
    dim3 pgrid(B, 4);
    pool_kernel<<<pgrid, 128>>>(Bb, batch, (float*)d_out, N, B);
}

// round 10
// speedup vs baseline: 2.1207x; 1.0879x over previous
#include <cuda_runtime.h>
#include <cuda_bf16.h>
#include <math.h>
#include <stdint.h>

// Problem constants (match reference_code)
#define NN 50000
#define EE 400000
#define BB 50

// ---------------- scratch (static device allocations: allowed) ----------------
__device__ __align__(16) float g_bufA[(size_t)NN * 512];
__device__ __align__(16) float g_bufB[(size_t)NN * 512];
__device__ __align__(16) float g_dinv[NN];
__device__ __align__(16) float g_self[NN];
__device__ __align__(16) float g_ew[EE];
__device__ __align__(16) float g_w4q[64 * 256];    // tf32-rounded W4
__device__ __align__(16) float g_w5q[256 * 512];   // tf32-rounded W5
__device__ int   g_degi[NN];
__device__ int   g_rowptr[NN + 1];
__device__ int   g_cursor[NN];
__device__ int   g_esrc[EE];
__device__ int   g_bsum[64];
__device__ int   g_is64;

__device__ __forceinline__ float* selbuf(int w) { return (w == 0) ? g_bufA : g_bufB; }

__device__ __forceinline__ int ld_idx(const void* p, long long i) {
    if (g_is64) return (int)((const long long*)p)[i];
    return ((const int*)p)[i];
}

__device__ __forceinline__ unsigned f2tf32(float x) {
    unsigned u;
    asm("cvt.rna.tf32.f32 %0, %1;" : "=r"(u) : "f"(x));
    return u;
}
__device__ __forceinline__ float rnd_tf32(float x) { return __uint_as_float(f2tf32(x)); }

__device__ __forceinline__ uint32_t smem_u32(const void* p) {
    uint32_t a;
    asm("{ .reg .u64 t; cvta.to.shared.u64 t, %1; cvt.u32.u64 %0, t; }" : "=r"(a) : "l"(p));
    return a;
}

// ---------------- dtype detection ----------------
__global__ void detect_kernel(const int* __restrict__ ei32) {
    if (threadIdx.x == 0 && blockIdx.x == 0) {
        int all0 = 1;
        for (int i = 1; i < 4096; i += 2) {
            if (ei32[i] != 0) { all0 = 0; break; }
        }
        g_is64 = all0;
    }
}

// ---------------- CSR build ----------------
__global__ void zero_degi_kernel(int N) {
    int t = blockIdx.x * blockDim.x + threadIdx.x;
    if (t < N) g_degi[t] = 0;
}

__global__ void deg_accum_kernel(const void* __restrict__ ei, int E) {
    int t = blockIdx.x * blockDim.x + threadIdx.x;
    if (t < E) atomicAdd(&g_degi[ld_idx(ei, (long long)E + t)], 1);
}

__global__ void scan_phase1(int N) {
    __shared__ int warp_tot[32];
    int i    = blockIdx.x * 1024 + threadIdx.x;
    int lane = threadIdx.x & 31, wid = threadIdx.x >> 5;
    int v = (i < N) ? g_degi[i] : 0;
    int incl = v;
#pragma unroll
    for (int off = 1; off < 32; off <<= 1) {
        int u = __shfl_up_sync(0xffffffffu, incl, off);
        if (lane >= off) incl += u;
    }
    if (lane == 31) warp_tot[wid] = incl;
    __syncthreads();
    if (wid == 0) {
        int w = warp_tot[lane];
#pragma unroll
        for (int off = 1; off < 32; off <<= 1) {
            int u = __shfl_up_sync(0xffffffffu, w, off);
            if (lane >= off) w += u;
        }
        warp_tot[lane] = w;
    }
    __syncthreads();
    if (wid > 0) incl += warp_tot[wid - 1];
    if (i < N) g_rowptr[i] = incl;
    if (threadIdx.x == 1023) g_bsum[blockIdx.x] = incl;
}

__global__ void scan_phase2(int nb) {
    __shared__ int w0tot;
    int t = threadIdx.x;
    int lane = t & 31, wid = t >> 5;
    int v = (t < nb) ? g_bsum[t] : 0;
    int incl = v;
#pragma unroll
    for (int off = 1; off < 32; off <<= 1) {
        int u = __shfl_up_sync(0xffffffffu, incl, off);
        if (lane >= off) incl += u;
    }
    if (t == 31) w0tot = incl;
    __syncthreads();
    int excl = incl - v + (wid == 1 ? w0tot : 0);
    if (t < nb) g_bsum[t] = excl;
}

__global__ void scan_phase3(int N) {
    int i = blockIdx.x * 1024 + threadIdx.x;
    if (i >= N) return;
    int v    = g_degi[i];
    int incl = g_rowptr[i] + g_bsum[blockIdx.x];
    int excl = incl - v;
    g_rowptr[i] = excl;
    g_cursor[i] = excl;
    float d  = (float)v + 1.0f;
    float di = rsqrtf(d);
    g_dinv[i] = di;
    g_self[i] = di * di;
    if (i == N - 1) g_rowptr[N] = incl;
}

__global__ void fill_kernel(const void* __restrict__ ei, int E) {
    int e = blockIdx.x * blockDim.x + threadIdx.x;
    if (e >= E) return;
    int s = ld_idx(ei, e);
    int d = ld_idx(ei, (long long)E + e);
    int p = atomicAdd(&g_cursor[d], 1);
    g_esrc[p] = s;
    g_ew[p]   = g_dinv[s] * g_dinv[d];
}

// ---------------- tf32-round weight copies ----------------
__global__ void round_w_kernel(const float* __restrict__ W, int n, int which) {
    int t = blockIdx.x * blockDim.x + threadIdx.x;
    if (t >= n) return;
    float* dst = (which == 4) ? g_w4q : g_w5q;
    dst[t] = rnd_tf32(W[t]);
}

// ---------------- layer 1 matmul (32 -> 8) ----------------
__global__ void mm1_kernel(const float* __restrict__ x,
                           const float* __restrict__ W, int N) {
    __shared__ float Ws[32 * 8];
    for (int i = threadIdx.x; i < 32 * 8; i += blockDim.x) Ws[i] = W[i];
    __syncthreads();
    int t = blockIdx.x * blockDim.x + threadIdx.x;
    int n = t >> 3, c = t & 7;
    if (n >= N) return;
    float acc = 0.0f;
    const float* xr = x + (size_t)n * 32;
#pragma unroll
    for (int k = 0; k < 32; k++) acc = fmaf(xr[k], Ws[k * 8 + c], acc);
    g_bufA[(size_t)n * 8 + c] = acc;
}

// ---------------- CSR gather aggregation ----------------
// RND: round outputs to tf32 (rna) — for GEMM consumers; numerically identical
// to converting inside the GEMM, enables raw cp.async there.
template <int D4, int BIAS, int RND>
__global__ void gather_agg_kernel(int inW, int outW,
                                  const float* __restrict__ bias, int N) {
    int t = blockIdx.x * blockDim.x + threadIdx.x;
    int n = t / D4, c4 = t % D4;
    if (n >= N) return;
    const float4* in4  = (const float4*)selbuf(inW);
    float4*       out4 = (float4*)selbuf(outW);

    float4 b = make_float4(0.f, 0.f, 0.f, 0.f);
    if (BIAS) b = ((const float4*)bias)[c4];

    float4 acc = in4[(size_t)n * D4 + c4];
    if (BIAS) {
        acc.x = fmaxf(acc.x + b.x, 0.f);
        acc.y = fmaxf(acc.y + b.y, 0.f);
        acc.z = fmaxf(acc.z + b.z, 0.f);
        acc.w = fmaxf(acc.w + b.w, 0.f);
    }
    float sn = g_self[n];
    acc.x *= sn; acc.y *= sn; acc.z *= sn; acc.w *= sn;

    int p0 = g_rowptr[n], p1 = g_rowptr[n + 1];
    for (int p = p0; p < p1; p++) {
        int   s = g_esrc[p];
        float w = g_ew[p];
        float4 v = in4[(size_t)s * D4 + c4];
        if (BIAS) {
            v.x = fmaxf(v.x + b.x, 0.f);
            v.y = fmaxf(v.y + b.y, 0.f);
            v.z = fmaxf(v.z + b.z, 0.f);
            v.w = fmaxf(v.w + b.w, 0.f);
        }
        acc.x = fmaf(v.x, w, acc.x);
        acc.y = fmaf(v.y, w, acc.y);
        acc.z = fmaf(v.z, w, acc.z);
        acc.w = fmaf(v.w, w, acc.w);
    }
    if (RND) {
        acc.x = rnd_tf32(acc.x);
        acc.y = rnd_tf32(acc.y);
        acc.z = rnd_tf32(acc.z);
        acc.w = rnd_tf32(acc.w);
    }
    out4[(size_t)n * D4 + c4] = acc;
}

// ---------------- small matmul ----------------
template <int K, int OUT>
__global__ void mm_small_kernel(int inW, int outW,
                                const float* __restrict__ W,
                                const float* __restrict__ bias, int N) {
    __shared__ float Ws[K * OUT];
    __shared__ float bs[OUT];
    for (int i = threadIdx.x; i < K * OUT; i += blockDim.x) Ws[i] = W[i];
    for (int i = threadIdx.x; i < OUT; i += blockDim.x) bs[i] = bias[i];
    __syncthreads();
    const float* A = selbuf(inW);
    float*       C = selbuf(outW);
    int t = blockIdx.x * blockDim.x + threadIdx.x;
    int n = t / OUT, c = t % OUT;
    if (n >= N) return;
    const float* ar = A + (size_t)n * K;
    float acc = 0.0f;
#pragma unroll
    for (int k = 0; k < K; k++) acc = fmaf(ar[k], Ws[k * OUT + c], acc);
    C[(size_t)n * OUT + c] = fmaxf(acc + bs[c], 0.0f);
}

// ---------------- TF32 mma.sync GEMM with cp.async 4-stage pipeline -----------
// C[N,OUT] = relu(A@W + b). A and Wq are tf32-pre-rounded fp32.
// BM=BN=128, BK=16, 256 thr = 8 warps (2M x 4N), warp tile 64x32, m16n8k8.
// smem: A[4][128][20] then B[4][16][136] floats (pads -> conflict-free frags,
// rows stay 16B-aligned for cp.async).
#define GSTAGES 4
#define A_PITCH 20
#define B_PITCH 136
#define A_STG (128 * A_PITCH)          // floats per A stage
#define B_STG (16 * B_PITCH)           // floats per B stage
#define GEMM_SMEM ((GSTAGES * (A_STG + B_STG)) * 4)   // 75776 bytes

__global__ __launch_bounds__(256, 2)
void mma_gemm_kernel(int inW, int outW, int wsel,
                     const float* __restrict__ bias,
                     int N, int K, int OUT) {
    extern __shared__ float smf[];
    const uint32_t sbase = smem_u32(smf);

    const float* A  = selbuf(inW);
    const float* Wq = (wsel == 4) ? g_w4q : g_w5q;
    float*       C  = selbuf(outW);

    const int tid    = threadIdx.x;
    const int lane   = tid & 31;
    const int warpId = tid >> 5;
    const int warpM  = warpId & 1;
    const int warpN  = warpId >> 1;
    const int gid    = lane >> 2;
    const int tig    = lane & 3;
    const int block_row = blockIdx.x * 128;
    const int block_col = blockIdx.y * 128;

    float c[4][4][4];
#pragma unroll
    for (int i = 0; i < 4; i++)
#pragma unroll
        for (int j = 0; j < 4; j++)
#pragma unroll
            for (int r = 0; r < 4; r++) c[i][j][r] = 0.0f;

    auto load_stage = [&](int st, int k0) {
#pragma unroll
        for (int it = 0; it < 2; it++) {
            int chunk = tid + it * 256;          // 0..511
            // A: 128 rows x 16 floats (4 chunks/row)
            {
                int r = chunk >> 2, c4 = (chunk & 3) * 4;
                int grow = block_row + r;
                const float* src = &A[(size_t)grow * K + k0 + c4];
                uint32_t dst = sbase + (st * A_STG + r * A_PITCH + c4) * 4;
                uint32_t pred = (grow < N) ? 1u : 0u;
                asm volatile(
                    "{ .reg .pred p; setp.ne.u32 p, %2, 0;\n\t"
                    "@p cp.async.cg.shared.global [%0], [%1], 16; }"
                    :: "r"(dst), "l"(src), "r"(pred) : "memory");
            }
            // B: 16 rows x 128 floats (32 chunks/row)
            {
                int r = chunk >> 5, c4 = (chunk & 31) * 4;
                const float* src = &Wq[(size_t)(k0 + r) * OUT + block_col + c4];
                uint32_t dst = sbase + (GSTAGES * A_STG + st * B_STG + r * B_PITCH + c4) * 4;
                asm volatile("cp.async.cg.shared.global [%0], [%1], 16;"
                             :: "r"(dst), "l"(src) : "memory");
            }
        }
    };

    const int ntiles = K >> 4;
    const int pre = (ntiles < 3) ? ntiles : 3;
    for (int st = 0; st < pre; st++) {
        load_stage(st, st * 16);
        asm volatile("cp.async.commit_group;" ::: "memory");
    }

    for (int ti = 0; ti < ntiles; ti++) {
        asm volatile("cp.async.wait_group 2;" ::: "memory");
        __syncthreads();
        int nxt = ti + 3;
        if (nxt < ntiles) load_stage(nxt & 3, nxt * 16);
        asm volatile("cp.async.commit_group;" ::: "memory");

        const int st = ti & 3;
        const float* As = &smf[st * A_STG];
        const float* Bs = &smf[GSTAGES * A_STG + st * B_STG];
#pragma unroll
        for (int k8 = 0; k8 < 2; k8++) {
            const int kb = k8 * 8;
            unsigned a[4][4], b[4][2];
#pragma unroll
            for (int mt = 0; mt < 4; mt++) {
                int mb = warpM * 64 + mt * 16;
                a[mt][0] = __float_as_uint(As[(mb + gid) * A_PITCH + kb + tig]);
                a[mt][1] = __float_as_uint(As[(mb + gid + 8) * A_PITCH + kb + tig]);
                a[mt][2] = __float_as_uint(As[(mb + gid) * A_PITCH + kb + tig + 4]);
                a[mt][3] = __float_as_uint(As[(mb + gid + 8) * A_PITCH + kb + tig + 4]);
            }
#pragma unroll
            for (int nt = 0; nt < 4; nt++) {
                int nb = warpN * 32 + nt * 8;
                b[nt][0] = __float_as_uint(Bs[(kb + tig) * B_PITCH + nb + gid]);
                b[nt][1] = __float_as_uint(Bs[(kb + tig + 4) * B_PITCH + nb + gid]);
            }
#pragma unroll
            for (int mt = 0; mt < 4; mt++)
#pragma unroll
                for (int nt = 0; nt < 4; nt++) {
                    asm volatile(
                        "mma.sync.aligned.m16n8k8.row.col.f32.tf32.tf32.f32 "
                        "{%0,%1,%2,%3}, {%4,%5,%6,%7}, {%8,%9}, {%0,%1,%2,%3};"
                        : "+f"(c[mt][nt][0]), "+f"(c[mt][nt][1]),
                          "+f"(c[mt][nt][2]), "+f"(c[mt][nt][3])
                        : "r"(a[mt][0]), "r"(a[mt][1]), "r"(a[mt][2]), "r"(a[mt][3]),
                          "r"(b[nt][0]), "r"(b[nt][1]));
                }
        }
    }

    // Epilogue
#pragma unroll
    for (int mt = 0; mt < 4; mt++) {
        int row0 = block_row + warpM * 64 + mt * 16 + gid;
#pragma unroll
        for (int nt = 0; nt < 4; nt++) {
            int col = block_col + warpN * 32 + nt * 8 + tig * 2;
            float bx = bias[col], by = bias[col + 1];
            if (row0 < N) {
                float2 o;
                o.x = fmaxf(c[mt][nt][0] + bx, 0.f);
                o.y = fmaxf(c[mt][nt][1] + by, 0.f);
                *(float2*)&C[(size_t)row0 * OUT + col] = o;
            }
            if (row0 + 8 < N) {
                float2 o;
                o.x = fmaxf(c[mt][nt][2] + bx, 0.f);
                o.y = fmaxf(c[mt][nt][3] + by, 0.f);
                *(float2*)&C[(size_t)(row0 + 8) * OUT + col] = o;
            }
        }
    }
}

// ---------------- mean pool over sorted batch ids ----------------
__device__ __forceinline__ int lower_bound_idx(const void* a, int n, int v) {
    int lo = 0, hi = n;
    while (lo < hi) {
        int m = (lo + hi) >> 1;
        if (ld_idx(a, m) < v) lo = m + 1; else hi = m;
    }
    return lo;
}

__global__ void pool_kernel(int inW,
                            const void* __restrict__ batch,
                            float* __restrict__ out, int N, int B) {
    const float* x = selbuf(inW);
    int b = blockIdx.x;
    int cbase = blockIdx.y * 128;
    __shared__ int s_lo, s_hi;
    if (threadIdx.x == 0) {
        s_lo = lower_bound_idx(batch, N, b);
        s_hi = lower_bound_idx(batch, N, b + 1);
    }
    __syncthreads();
    int lo = s_lo, hi = s_hi;
    float inv = 1.0f / fmaxf((float)(hi - lo), 1.0f);
    int c = cbase + threadIdx.x;
    float s = 0.0f;
    for (int n = lo; n < hi; n++) s += x[(size_t)n * 512 + c];
    out[(size_t)b * 512 + c] = s * inv;
}

// ---------------- launch ----------------
static inline unsigned gr(long long n, int b) { return (unsigned)((n + b - 1) / b); }

extern "C" void kernel_launch(void* const* d_in, const int* in_sizes, int n_in,
                              void* d_out, int out_size) {
    const float* x     = (const float*)d_in[0];
    const void*  ei    = d_in[1];
    const void*  batch = d_in[2];
    const float *W1 = (const float*)d_in[3],  *b1 = (const float*)d_in[4];
    const float *W2 = (const float*)d_in[5],  *b2 = (const float*)d_in[6];
    const float *W3 = (const float*)d_in[7],  *b3 = (const float*)d_in[8];
    const float *W4 = (const float*)d_in[9],  *b4 = (const float*)d_in[10];
    const float *W5 = (const float*)d_in[11], *b5 = (const float*)d_in[12];

    const int N = in_sizes[0] / 32;
    const int E = in_sizes[1] / 2;
    const int B = out_size / 512;

    const int TB = 256;
    const int A = 0, Bb = 1;
    const int nb = (N + 1023) / 1024;

    static int smem_set = 0;
    if (!smem_set) {
        cudaFuncSetAttribute(mma_gemm_kernel, cudaFuncAttributeMaxDynamicSharedMemorySize, GEMM_SMEM);
        smem_set = 1;
    }

    // index dtype detection + CSR build + norms + weight rounding
    detect_kernel<<<1, 32>>>((const int*)ei);
    zero_degi_kernel<<<gr(N, TB), TB>>>(N);
    deg_accum_kernel<<<gr(E, TB), TB>>>(ei, E);
    scan_phase1<<<nb, 1024>>>(N);
    scan_phase2<<<1, 64>>>(nb);
    scan_phase3<<<nb, 1024>>>(N);
    fill_kernel<<<gr(E, TB), TB>>>(ei, E);
    round_w_kernel<<<gr(64 * 256, TB), TB>>>(W4, 64 * 256, 4);
    round_w_kernel<<<gr(256 * 512, TB), TB>>>(W5, 256 * 512, 5);

    // Layer 1 (32 -> 8)
    mm1_kernel<<<gr((long long)N * 8, TB), TB>>>(x, W1, N);
    gather_agg_kernel<2, 0, 0><<<gr((long long)N * 2, TB), TB>>>(A, Bb, nullptr, N);

    // Layer 2 (8 -> 16)
    gather_agg_kernel<2, 1, 0><<<gr((long long)N * 2, TB), TB>>>(Bb, A, b1, N);
    mm_small_kernel<8, 16><<<gr((long long)N * 16, TB), TB>>>(A, Bb, W2, b2, N);

    // Layer 3 (16 -> 64)
    gather_agg_kernel<4, 0, 0><<<gr((long long)N * 4, TB), TB>>>(Bb, A, nullptr, N);
    mm_small_kernel<16, 64><<<gr((long long)N * 64, TB), TB>>>(A, Bb, W3, b3, N);

    // Layer 4 (64 -> 256): aggregate (tf32-rounded) then pipelined mma GEMM.
    gather_agg_kernel<16, 0, 1><<<gr((long long)N * 16, TB), TB>>>(Bb, A, nullptr, N);
    {
        dim3 grid(gr(N, 128), 256 / 128);
        mma_gemm_kernel<<<grid, 256, GEMM_SMEM>>>(A, Bb, 4, b4, N, 64, 256);
    }

    // Layer 5 (256 -> 512): aggregate (tf32-rounded) then pipelined mma GEMM.
    gather_agg_kernel<64, 0, 1><<<gr((long long)N * 64, TB), TB>>>(Bb, A, nullptr, N);
    {
        dim3 grid(gr(N, 128), 512 / 128);
        mma_gemm_kernel<<<grid, 256, GEMM_SMEM>>>(A, Bb, 5, b5, N, 256, 512);
    }

    // Global mean pool
    dim3 pgrid(B, 4);
    pool_kernel<<<pgrid, 128>>>(Bb, batch, (float*)d_out, N, B);
}

// round 11
// speedup vs baseline: 2.1878x; 1.0317x over previous
#include <cuda_runtime.h>
#include <cuda_fp16.h>
#include <math.h>
#include <stdint.h>

// Problem constants (match reference_code)
#define NN 50000
#define EE 400000
#define BB 50

// ---------------- scratch (static device allocations: allowed) ----------------
__device__ __align__(16) float  g_bufA[(size_t)NN * 512];
__device__ __align__(16) float  g_bufB[(size_t)NN * 512];
__device__ __align__(16) __half g_bufH[(size_t)NN * 256];   // half GEMM input
__device__ __align__(16) float  g_dinv[NN];
__device__ __align__(16) float  g_self[NN];
__device__ __align__(16) float  g_ew[EE];
__device__ __align__(16) __half g_w4h[256 * 64];    // W4^T as half [256][64]
__device__ __align__(16) __half g_w5h[512 * 256];   // W5^T as half [512][256]
__device__ int   g_degi[NN];
__device__ int   g_rowptr[NN + 1];
__device__ int   g_cursor[NN];
__device__ int   g_esrc[EE];
__device__ int   g_bsum[64];
__device__ int   g_is64;

__device__ __forceinline__ float* selbuf(int w) { return (w == 0) ? g_bufA : g_bufB; }

__device__ __forceinline__ int ld_idx(const void* p, long long i) {
    if (g_is64) return (int)((const long long*)p)[i];
    return ((const int*)p)[i];
}

__device__ __forceinline__ uint32_t smem_u32(const void* p) {
    uint32_t a;
    asm("{ .reg .u64 t; cvta.to.shared.u64 t, %1; cvt.u32.u64 %0, t; }" : "=r"(a) : "l"(p));
    return a;
}

// ---------------- dtype detection ----------------
__global__ void detect_kernel(const int* __restrict__ ei32) {
    if (threadIdx.x == 0 && blockIdx.x == 0) {
        int all0 = 1;
        for (int i = 1; i < 4096; i += 2) {
            if (ei32[i] != 0) { all0 = 0; break; }
        }
        g_is64 = all0;
    }
}

// ---------------- CSR build ----------------
__global__ void zero_degi_kernel(int N) {
    int t = blockIdx.x * blockDim.x + threadIdx.x;
    if (t < N) g_degi[t] = 0;
}

__global__ void deg_accum_kernel(const void* __restrict__ ei, int E) {
    int t = blockIdx.x * blockDim.x + threadIdx.x;
    if (t < E) atomicAdd(&g_degi[ld_idx(ei, (long long)E + t)], 1);
}

__global__ void scan_phase1(int N) {
    __shared__ int warp_tot[32];
    int i    = blockIdx.x * 1024 + threadIdx.x;
    int lane = threadIdx.x & 31, wid = threadIdx.x >> 5;
    int v = (i < N) ? g_degi[i] : 0;
    int incl = v;
#pragma unroll
    for (int off = 1; off < 32; off <<= 1) {
        int u = __shfl_up_sync(0xffffffffu, incl, off);
        if (lane >= off) incl += u;
    }
    if (lane == 31) warp_tot[wid] = incl;
    __syncthreads();
    if (wid == 0) {
        int w = warp_tot[lane];
#pragma unroll
        for (int off = 1; off < 32; off <<= 1) {
            int u = __shfl_up_sync(0xffffffffu, w, off);
            if (lane >= off) w += u;
        }
        warp_tot[lane] = w;
    }
    __syncthreads();
    if (wid > 0) incl += warp_tot[wid - 1];
    if (i < N) g_rowptr[i] = incl;
    if (threadIdx.x == 1023) g_bsum[blockIdx.x] = incl;
}

__global__ void scan_phase2(int nb) {
    __shared__ int w0tot;
    int t = threadIdx.x;
    int lane = t & 31, wid = t >> 5;
    int v = (t < nb) ? g_bsum[t] : 0;
    int incl = v;
#pragma unroll
    for (int off = 1; off < 32; off <<= 1) {
        int u = __shfl_up_sync(0xffffffffu, incl, off);
        if (lane >= off) incl += u;
    }
    if (t == 31) w0tot = incl;
    __syncthreads();
    int excl = incl - v + (wid == 1 ? w0tot : 0);
    if (t < nb) g_bsum[t] = excl;
}

__global__ void scan_phase3(int N) {
    int i = blockIdx.x * 1024 + threadIdx.x;
    if (i >= N) return;
    int v    = g_degi[i];
    int incl = g_rowptr[i] + g_bsum[blockIdx.x];
    int excl = incl - v;
    g_rowptr[i] = excl;
    g_cursor[i] = excl;
    float d  = (float)v + 1.0f;
    float di = rsqrtf(d);
    g_dinv[i] = di;
    g_self[i] = di * di;
    if (i == N - 1) g_rowptr[N] = incl;
}

__global__ void fill_kernel(const void* __restrict__ ei, int E) {
    int e = blockIdx.x * blockDim.x + threadIdx.x;
    if (e >= E) return;
    int s = ld_idx(ei, e);
    int d = ld_idx(ei, (long long)E + e);
    int p = atomicAdd(&g_cursor[d], 1);
    g_esrc[p] = s;
    g_ew[p]   = g_dinv[s] * g_dinv[d];
}

// ---------------- transpose+convert W [R][C] fp32 -> Wt [C][R] half ----------
__global__ void trconv_w_kernel(const float* __restrict__ in,
                                __half* __restrict__ out, int R, int Cc) {
    __shared__ float tile[32][33];
    int c0 = blockIdx.x * 32, r0 = blockIdx.y * 32;
    int tx = threadIdx.x;
    for (int i = threadIdx.y; i < 32; i += 8) {
        int r = r0 + i, c = c0 + tx;
        tile[i][tx] = (r < R && c < Cc) ? in[(size_t)r * Cc + c] : 0.f;
    }
    __syncthreads();
    for (int i = threadIdx.y; i < 32; i += 8) {
        int orow = c0 + i, oc = r0 + tx;
        if (orow < Cc && oc < R) out[(size_t)orow * R + oc] = __float2half_rn(tile[tx][i]);
    }
}

// ---------------- layer 1 matmul (32 -> 8) ----------------
__global__ void mm1_kernel(const float* __restrict__ x,
                           const float* __restrict__ W, int N) {
    __shared__ float Ws[32 * 8];
    for (int i = threadIdx.x; i < 32 * 8; i += blockDim.x) Ws[i] = W[i];
    __syncthreads();
    int t = blockIdx.x * blockDim.x + threadIdx.x;
    int n = t >> 3, c = t & 7;
    if (n >= N) return;
    float acc = 0.0f;
    const float* xr = x + (size_t)n * 32;
#pragma unroll
    for (int k = 0; k < 32; k++) acc = fmaf(xr[k], Ws[k * 8 + c], acc);
    g_bufA[(size_t)n * 8 + c] = acc;
}

// ---------------- CSR gather aggregation (fp32 out) ----------------
template <int D4, int BIAS>
__global__ void gather_agg_kernel(int inW, int outW,
                                  const float* __restrict__ bias, int N) {
    int t = blockIdx.x * blockDim.x + threadIdx.x;
    int n = t / D4, c4 = t % D4;
    if (n >= N) return;
    const float4* in4  = (const float4*)selbuf(inW);
    float4*       out4 = (float4*)selbuf(outW);

    float4 b = make_float4(0.f, 0.f, 0.f, 0.f);
    if (BIAS) b = ((const float4*)bias)[c4];

    float4 acc = in4[(size_t)n * D4 + c4];
    if (BIAS) {
        acc.x = fmaxf(acc.x + b.x, 0.f);
        acc.y = fmaxf(acc.y + b.y, 0.f);
        acc.z = fmaxf(acc.z + b.z, 0.f);
        acc.w = fmaxf(acc.w + b.w, 0.f);
    }
    float sn = g_self[n];
    acc.x *= sn; acc.y *= sn; acc.z *= sn; acc.w *= sn;

    int p0 = g_rowptr[n], p1 = g_rowptr[n + 1];
    for (int p = p0; p < p1; p++) {
        int   s = g_esrc[p];
        float w = g_ew[p];
        float4 v = in4[(size_t)s * D4 + c4];
        if (BIAS) {
            v.x = fmaxf(v.x + b.x, 0.f);
            v.y = fmaxf(v.y + b.y, 0.f);
            v.z = fmaxf(v.z + b.z, 0.f);
            v.w = fmaxf(v.w + b.w, 0.f);
        }
        acc.x = fmaf(v.x, w, acc.x);
        acc.y = fmaf(v.y, w, acc.y);
        acc.z = fmaf(v.z, w, acc.z);
        acc.w = fmaf(v.w, w, acc.w);
    }
    out4[(size_t)n * D4 + c4] = acc;
}

// ---------------- CSR gather aggregation (half out, for GEMM input) ----------
struct alignas(8) h4 { __half2 a, b; };
template <int D4>
__global__ void gather_agg_h_kernel(int inW, int N) {
    int t = blockIdx.x * blockDim.x + threadIdx.x;
    int n = t / D4, c4 = t % D4;
    if (n >= N) return;
    const float4* in4 = (const float4*)selbuf(inW);

    float4 acc = in4[(size_t)n * D4 + c4];
    float sn = g_self[n];
    acc.x *= sn; acc.y *= sn; acc.z *= sn; acc.w *= sn;

    int p0 = g_rowptr[n], p1 = g_rowptr[n + 1];
    for (int p = p0; p < p1; p++) {
        int   s = g_esrc[p];
        float w = g_ew[p];
        float4 v = in4[(size_t)s * D4 + c4];
        acc.x = fmaf(v.x, w, acc.x);
        acc.y = fmaf(v.y, w, acc.y);
        acc.z = fmaf(v.z, w, acc.z);
        acc.w = fmaf(v.w, w, acc.w);
    }
    h4 o;
    o.a = __float22half2_rn(make_float2(acc.x, acc.y));
    o.b = __float22half2_rn(make_float2(acc.z, acc.w));
    ((h4*)g_bufH)[(size_t)n * D4 + c4] = o;
}

// ---------------- small matmul ----------------
template <int K, int OUT>
__global__ void mm_small_kernel(int inW, int outW,
                                const float* __restrict__ W,
                                const float* __restrict__ bias, int N) {
    __shared__ float Ws[K * OUT];
    __shared__ float bs[OUT];
    for (int i = threadIdx.x; i < K * OUT; i += blockDim.x) Ws[i] = W[i];
    for (int i = threadIdx.x; i < OUT; i += blockDim.x) bs[i] = bias[i];
    __syncthreads();
    const float* A = selbuf(inW);
    float*       C = selbuf(outW);
    int t = blockIdx.x * blockDim.x + threadIdx.x;
    int n = t / OUT, c = t % OUT;
    if (n >= N) return;
    const float* ar = A + (size_t)n * K;
    float acc = 0.0f;
#pragma unroll
    for (int k = 0; k < K; k++) acc = fmaf(ar[k], Ws[k * OUT + c], acc);
    C[(size_t)n * OUT + c] = fmaxf(acc + bs[c], 0.0f);
}

// ---------------- fp16 m16n8k16 GEMM with cp.async 4-stage pipeline ----------
// C[N,OUT] = relu(Ah@W + b), Ah = g_bufH [N][K] half, Wt = [OUT][K] half.
// BM=BN=128, BK=16, 256 thr = 8 warps (2M x 4N), warp tile 64x32.
// smem tiles pitch 24 halves (48B rows): conflict-free frags, 16B-aligned rows.
#define HSTAGES 4
#define H_PITCH 24
#define H_STG (128 * H_PITCH)                     // halves per tile stage
#define HGEMM_SMEM (HSTAGES * 2 * H_STG * 2)      // 49152 bytes

__global__ __launch_bounds__(256, 2)
void hgemm_kernel(int outW, int wsel,
                  const float* __restrict__ bias,
                  int N, int K, int OUT) {
    extern __shared__ __half smh[];
    const uint32_t sbase = smem_u32(smh);

    const __half* Ah = g_bufH;
    const __half* Wt = (wsel == 4) ? g_w4h : g_w5h;
    float*        C  = selbuf(outW);

    const int tid    = threadIdx.x;
    const int lane   = tid & 31;
    const int warpId = tid >> 5;
    const int warpM  = warpId & 1;
    const int warpN  = warpId >> 1;
    const int gid    = lane >> 2;
    const int tig    = lane & 3;
    const int block_row = blockIdx.x * 128;
    const int block_col = blockIdx.y * 128;

    float c[4][4][4];
#pragma unroll
    for (int i = 0; i < 4; i++)
#pragma unroll
        for (int j = 0; j < 4; j++)
#pragma unroll
            for (int r = 0; r < 4; r++) c[i][j][r] = 0.0f;

    auto load_stage = [&](int st, int k0) {
#pragma unroll
        for (int it = 0; it < 2; it++) {
            int chunk = tid + it * 256;              // 0..511
            if (chunk < 256) {
                // A: 128 rows x 16 halves (2 x 16B chunks per row)
                int r = chunk >> 1, c8 = (chunk & 1) * 8;
                int grow = block_row + r;
                const __half* src = &Ah[(size_t)grow * K + k0 + c8];
                uint32_t dst = sbase + (st * H_STG + r * H_PITCH + c8) * 2;
                uint32_t pred = (grow < N) ? 1u : 0u;
                asm volatile(
                    "{ .reg .pred p; setp.ne.u32 p, %2, 0;\n\t"
                    "@p cp.async.cg.shared.global [%0], [%1], 16; }"
                    :: "r"(dst), "l"(src), "r"(pred) : "memory");
            } else {
                // B: 128 n-rows x 16 halves
                int c2 = chunk - 256;
                int r = c2 >> 1, c8 = (c2 & 1) * 8;
                const __half* src = &Wt[(size_t)(block_col + r) * K + k0 + c8];
                uint32_t dst = sbase + (HSTAGES * H_STG + st * H_STG + r * H_PITCH + c8) * 2;
                asm volatile("cp.async.cg.shared.global [%0], [%1], 16;"
                             :: "r"(dst), "l"(src) : "memory");
            }
        }
    };

    const int ntiles = K >> 4;
    const int pre = (ntiles < 3) ? ntiles : 3;
    for (int st = 0; st < pre; st++) {
        load_stage(st, st * 16);
        asm volatile("cp.async.commit_group;" ::: "memory");
    }

    for (int ti = 0; ti < ntiles; ti++) {
        asm volatile("cp.async.wait_group 2;" ::: "memory");
        __syncthreads();
        int nxt = ti + 3;
        if (nxt < ntiles) load_stage(nxt & 3, nxt * 16);
        asm volatile("cp.async.commit_group;" ::: "memory");

        const int st = ti & 3;
        const __half* As = &smh[st * H_STG];
        const __half* Bs = &smh[HSTAGES * H_STG + st * H_STG];

        unsigned a[4][4], b[4][2];
#pragma unroll
        for (int mt = 0; mt < 4; mt++) {
            int mb = warpM * 64 + mt * 16;
            a[mt][0] = *(const unsigned*)&As[(mb + gid) * H_PITCH + 2 * tig];
            a[mt][1] = *(const unsigned*)&As[(mb + gid + 8) * H_PITCH + 2 * tig];
            a[mt][2] = *(const unsigned*)&As[(mb + gid) * H_PITCH + 2 * tig + 8];
            a[mt][3] = *(const unsigned*)&As[(mb + gid + 8) * H_PITCH + 2 * tig + 8];
        }
#pragma unroll
        for (int nt = 0; nt < 4; nt++) {
            int nb = warpN * 32 + nt * 8;
            b[nt][0] = *(const unsigned*)&Bs[(nb + gid) * H_PITCH + 2 * tig];
            b[nt][1] = *(const unsigned*)&Bs[(nb + gid) * H_PITCH + 2 * tig + 8];
        }
#pragma unroll
        for (int mt = 0; mt < 4; mt++)
#pragma unroll
            for (int nt = 0; nt < 4; nt++) {
                asm volatile(
                    "mma.sync.aligned.m16n8k16.row.col.f32.f16.f16.f32 "
                    "{%0,%1,%2,%3}, {%4,%5,%6,%7}, {%8,%9}, {%0,%1,%2,%3};"
                    : "+f"(c[mt][nt][0]), "+f"(c[mt][nt][1]),
                      "+f"(c[mt][nt][2]), "+f"(c[mt][nt][3])
                    : "r"(a[mt][0]), "r"(a[mt][1]), "r"(a[mt][2]), "r"(a[mt][3]),
                      "r"(b[nt][0]), "r"(b[nt][1]));
            }
    }

    // Epilogue: c0,c1 -> (row, col..col+1); c2,c3 -> (row+8, ..)
#pragma unroll
    for (int mt = 0; mt < 4; mt++) {
        int row0 = block_row + warpM * 64 + mt * 16 + gid;
#pragma unroll
        for (int nt = 0; nt < 4; nt++) {
            int col = block_col + warpN * 32 + nt * 8 + tig * 2;
            float bx = bias[col], by = bias[col + 1];
            if (row0 < N) {
                float2 o;
                o.x = fmaxf(c[mt][nt][0] + bx, 0.f);
                o.y = fmaxf(c[mt][nt][1] + by, 0.f);
                *(float2*)&C[(size_t)row0 * OUT + col] = o;
            }
            if (row0 + 8 < N) {
                float2 o;
                o.x = fmaxf(c[mt][nt][2] + bx, 0.f);
                o.y = fmaxf(c[mt][nt][3] + by, 0.f);
                *(float2*)&C[(size_t)(row0 + 8) * OUT + col] = o;
            }
        }
    }
}

// ---------------- mean pool over sorted batch ids ----------------
__device__ __forceinline__ int lower_bound_idx(const void* a, int n, int v) {
    int lo = 0, hi = n;
    while (lo < hi) {
        int m = (lo + hi) >> 1;
        if (ld_idx(a, m) < v) lo = m + 1; else hi = m;
    }
    return lo;
}

__global__ void pool_kernel(int inW,
                            const void* __restrict__ batch,
                            float* __restrict__ out, int N, int B) {
    const float* x = selbuf(inW);
    int b = blockIdx.x;
    int cbase = blockIdx.y * 128;
    __shared__ int s_lo, s_hi;
    if (threadIdx.x == 0) {
        s_lo = lower_bound_idx(batch, N, b);
        s_hi = lower_bound_idx(batch, N, b + 1);
    }
    __syncthreads();
    int lo = s_lo, hi = s_hi;
    float inv = 1.0f / fmaxf((float)(hi - lo), 1.0f);
    int c = cbase + threadIdx.x;
    float s0 = 0.f, s1 = 0.f, s2 = 0.f, s3 = 0.f;
    int n = lo;
    for (; n + 3 < hi; n += 4) {
        s0 += x[(size_t)n * 512 + c];
        s1 += x[(size_t)(n + 1) * 512 + c];
        s2 += x[(size_t)(n + 2) * 512 + c];
        s3 += x[(size_t)(n + 3) * 512 + c];
    }
    for (; n < hi; n++) s0 += x[(size_t)n * 512 + c];
    out[(size_t)b * 512 + c] = (s0 + s1 + s2 + s3) * inv;
}

// ---------------- launch ----------------
static inline unsigned gr(long long n, int b) { return (unsigned)((n + b - 1) / b); }

extern "C" void kernel_launch(void* const* d_in, const int* in_sizes, int n_in,
                              void* d_out, int out_size) {
    const float* x     = (const float*)d_in[0];
    const void*  ei    = d_in[1];
    const void*  batch = d_in[2];
    const float *W1 = (const float*)d_in[3],  *b1 = (const float*)d_in[4];
    const float *W2 = (const float*)d_in[5],  *b2 = (const float*)d_in[6];
    const float *W3 = (const float*)d_in[7],  *b3 = (const float*)d_in[8];
    const float *W4 = (const float*)d_in[9],  *b4 = (const float*)d_in[10];
    const float *W5 = (const float*)d_in[11], *b5 = (const float*)d_in[12];

    const int N = in_sizes[0] / 32;
    const int E = in_sizes[1] / 2;
    const int B = out_size / 512;

    const int TB = 256;
    const int A = 0, Bb = 1;
    const int nb = (N + 1023) / 1024;

    static int smem_set = 0;
    if (!smem_set) {
        cudaFuncSetAttribute(hgemm_kernel, cudaFuncAttributeMaxDynamicSharedMemorySize, HGEMM_SMEM);
        smem_set = 1;
    }

    __half *w4h, *w5h;
    cudaGetSymbolAddress((void**)&w4h, g_w4h);
    cudaGetSymbolAddress((void**)&w5h, g_w5h);

    // index dtype detection + CSR build + norms + weight transpose/convert
    detect_kernel<<<1, 32>>>((const int*)ei);
    zero_degi_kernel<<<gr(N, TB), TB>>>(N);
    deg_accum_kernel<<<gr(E, TB), TB>>>(ei, E);
    scan_phase1<<<nb, 1024>>>(N);
    scan_phase2<<<1, 64>>>(nb);
    scan_phase3<<<nb, 1024>>>(N);
    fill_kernel<<<gr(E, TB), TB>>>(ei, E);
    {
        dim3 t(32, 8);
        trconv_w_kernel<<<dim3(256 / 32, 64 / 32), t>>>(W4, w4h, 64, 256);
        trconv_w_kernel<<<dim3(512 / 32, 256 / 32), t>>>(W5, w5h, 256, 512);
    }

    // Layer 1 (32 -> 8)
    mm1_kernel<<<gr((long long)N * 8, TB), TB>>>(x, W1, N);
    gather_agg_kernel<2, 0><<<gr((long long)N * 2, TB), TB>>>(A, Bb, nullptr, N);

    // Layer 2 (8 -> 16)
    gather_agg_kernel<2, 1><<<gr((long long)N * 2, TB), TB>>>(Bb, A, b1, N);
    mm_small_kernel<8, 16><<<gr((long long)N * 16, TB), TB>>>(A, Bb, W2, b2, N);

    // Layer 3 (16 -> 64)
    gather_agg_kernel<4, 0><<<gr((long long)N * 4, TB), TB>>>(Bb, A, nullptr, N);
    mm_small_kernel<16, 64><<<gr((long long)N * 64, TB), TB>>>(A, Bb, W3, b3, N);

    // Layer 4 (64 -> 256): aggregate -> half, then fp16 GEMM.
    gather_agg_h_kernel<16><<<gr((long long)N * 16, TB), TB>>>(Bb, N);
    {
        dim3 grid(gr(N, 128), 256 / 128);
        hgemm_kernel<<<grid, 256, HGEMM_SMEM>>>(Bb, 4, b4, N, 64, 256);
    }

    // Layer 5 (256 -> 512): aggregate -> half, then fp16 GEMM.
    gather_agg_h_kernel<64><<<gr((long long)N * 64, TB), TB>>>(Bb, N);
    {
        dim3 grid(gr(N, 128), 512 / 128);
        hgemm_kernel<<<grid, 256, HGEMM_SMEM>>>(Bb, 5, b5, N, 256, 512);
    }

    // Global mean pool
    dim3 pgrid(B, 4);
    pool_kernel<<<pgrid, 128>>>(Bb, batch, (float*)d_out, N, B);
}

// round 12
// speedup vs baseline: 2.2805x; 1.0424x over previous
#include <cuda_runtime.h>
#include <cuda_fp16.h>
#include <math.h>
#include <stdint.h>

// Problem constants (match reference_code)
#define NN 50000
#define EE 400000
#define BB 50

// ---------------- scratch (static device allocations: allowed) ----------------
__device__ __align__(16) float  g_bufA[(size_t)NN * 512];
__device__ __align__(16) float  g_bufB[(size_t)NN * 512];
__device__ __align__(16) __half g_bufH[(size_t)NN * 256];   // gather output (GEMM in)
__device__ __align__(16) __half g_bufH2[(size_t)NN * 256];  // L4 GEMM half output (x4)
__device__ __align__(16) float  g_dinv[NN];
__device__ __align__(16) float  g_self[NN];
__device__ __align__(16) float  g_ew[EE];
__device__ __align__(16) __half g_w4h[256 * 64];    // W4^T as half [256][64]
__device__ __align__(16) __half g_w5h[512 * 256];   // W5^T as half [512][256]
__device__ int   g_degi[NN];
__device__ int   g_rowptr[NN + 1];
__device__ int   g_cursor[NN];
__device__ int   g_esrc[EE];
__device__ int   g_bsum[64];
__device__ int   g_is64;

__device__ __forceinline__ float* selbuf(int w) { return (w == 0) ? g_bufA : g_bufB; }

__device__ __forceinline__ int ld_idx(const void* p, long long i) {
    if (g_is64) return (int)((const long long*)p)[i];
    return ((const int*)p)[i];
}

__device__ __forceinline__ uint32_t smem_u32(const void* p) {
    uint32_t a;
    asm("{ .reg .u64 t; cvta.to.shared.u64 t, %1; cvt.u32.u64 %0, t; }" : "=r"(a) : "l"(p));
    return a;
}

// ---------------- dtype detection ----------------
__global__ void detect_kernel(const int* __restrict__ ei32) {
    if (threadIdx.x == 0 && blockIdx.x == 0) {
        int all0 = 1;
        for (int i = 1; i < 4096; i += 2) {
            if (ei32[i] != 0) { all0 = 0; break; }
        }
        g_is64 = all0;
    }
}

// ---------------- CSR build ----------------
__global__ void zero_degi_kernel(int N) {
    int t = blockIdx.x * blockDim.x + threadIdx.x;
    if (t < N) g_degi[t] = 0;
}

__global__ void deg_accum_kernel(const void* __restrict__ ei, int E) {
    int t = blockIdx.x * blockDim.x + threadIdx.x;
    if (t < E) atomicAdd(&g_degi[ld_idx(ei, (long long)E + t)], 1);
}

__global__ void scan_phase1(int N) {
    __shared__ int warp_tot[32];
    int i    = blockIdx.x * 1024 + threadIdx.x;
    int lane = threadIdx.x & 31, wid = threadIdx.x >> 5;
    int v = (i < N) ? g_degi[i] : 0;
    int incl = v;
#pragma unroll
    for (int off = 1; off < 32; off <<= 1) {
        int u = __shfl_up_sync(0xffffffffu, incl, off);
        if (lane >= off) incl += u;
    }
    if (lane == 31) warp_tot[wid] = incl;
    __syncthreads();
    if (wid == 0) {
        int w = warp_tot[lane];
#pragma unroll
        for (int off = 1; off < 32; off <<= 1) {
            int u = __shfl_up_sync(0xffffffffu, w, off);
            if (lane >= off) w += u;
        }
        warp_tot[lane] = w;
    }
    __syncthreads();
    if (wid > 0) incl += warp_tot[wid - 1];
    if (i < N) g_rowptr[i] = incl;
    if (threadIdx.x == 1023) g_bsum[blockIdx.x] = incl;
}

__global__ void scan_phase2(int nb) {
    __shared__ int w0tot;
    int t = threadIdx.x;
    int lane = t & 31, wid = t >> 5;
    int v = (t < nb) ? g_bsum[t] : 0;
    int incl = v;
#pragma unroll
    for (int off = 1; off < 32; off <<= 1) {
        int u = __shfl_up_sync(0xffffffffu, incl, off);
        if (lane >= off) incl += u;
    }
    if (t == 31) w0tot = incl;
    __syncthreads();
    int excl = incl - v + (wid == 1 ? w0tot : 0);
    if (t < nb) g_bsum[t] = excl;
}

__global__ void scan_phase3(int N) {
    int i = blockIdx.x * 1024 + threadIdx.x;
    if (i >= N) return;
    int v    = g_degi[i];
    int incl = g_rowptr[i] + g_bsum[blockIdx.x];
    int excl = incl - v;
    g_rowptr[i] = excl;
    g_cursor[i] = excl;
    float d  = (float)v + 1.0f;
    float di = rsqrtf(d);
    g_dinv[i] = di;
    g_self[i] = di * di;
    if (i == N - 1) g_rowptr[N] = incl;
}

__global__ void fill_kernel(const void* __restrict__ ei, int E) {
    int e = blockIdx.x * blockDim.x + threadIdx.x;
    if (e >= E) return;
    int s = ld_idx(ei, e);
    int d = ld_idx(ei, (long long)E + e);
    int p = atomicAdd(&g_cursor[d], 1);
    g_esrc[p] = s;
    g_ew[p]   = g_dinv[s] * g_dinv[d];
}

// ---------------- transpose+convert W [R][C] fp32 -> Wt [C][R] half ----------
__global__ void trconv_w_kernel(const float* __restrict__ in,
                                __half* __restrict__ out, int R, int Cc) {
    __shared__ float tile[32][33];
    int c0 = blockIdx.x * 32, r0 = blockIdx.y * 32;
    int tx = threadIdx.x;
    for (int i = threadIdx.y; i < 32; i += 8) {
        int r = r0 + i, c = c0 + tx;
        tile[i][tx] = (r < R && c < Cc) ? in[(size_t)r * Cc + c] : 0.f;
    }
    __syncthreads();
    for (int i = threadIdx.y; i < 32; i += 8) {
        int orow = c0 + i, oc = r0 + tx;
        if (orow < Cc && oc < R) out[(size_t)orow * R + oc] = __float2half_rn(tile[tx][i]);
    }
}

// ---------------- layer 1 matmul (32 -> 8) ----------------
__global__ void mm1_kernel(const float* __restrict__ x,
                           const float* __restrict__ W, int N) {
    __shared__ float Ws[32 * 8];
    for (int i = threadIdx.x; i < 32 * 8; i += blockDim.x) Ws[i] = W[i];
    __syncthreads();
    int t = blockIdx.x * blockDim.x + threadIdx.x;
    int n = t >> 3, c = t & 7;
    if (n >= N) return;
    float acc = 0.0f;
    const float* xr = x + (size_t)n * 32;
#pragma unroll
    for (int k = 0; k < 32; k++) acc = fmaf(xr[k], Ws[k * 8 + c], acc);
    g_bufA[(size_t)n * 8 + c] = acc;
}

// ---------------- CSR gather aggregation (fp32 in/out) ----------------
template <int D4, int BIAS>
__global__ void gather_agg_kernel(int inW, int outW,
                                  const float* __restrict__ bias, int N) {
    int t = blockIdx.x * blockDim.x + threadIdx.x;
    int n = t / D4, c4 = t % D4;
    if (n >= N) return;
    const float4* in4  = (const float4*)selbuf(inW);
    float4*       out4 = (float4*)selbuf(outW);

    float4 b = make_float4(0.f, 0.f, 0.f, 0.f);
    if (BIAS) b = ((const float4*)bias)[c4];

    float4 acc = in4[(size_t)n * D4 + c4];
    if (BIAS) {
        acc.x = fmaxf(acc.x + b.x, 0.f);
        acc.y = fmaxf(acc.y + b.y, 0.f);
        acc.z = fmaxf(acc.z + b.z, 0.f);
        acc.w = fmaxf(acc.w + b.w, 0.f);
    }
    float sn = g_self[n];
    acc.x *= sn; acc.y *= sn; acc.z *= sn; acc.w *= sn;

    int p0 = g_rowptr[n], p1 = g_rowptr[n + 1];
    for (int p = p0; p < p1; p++) {
        int   s = g_esrc[p];
        float w = g_ew[p];
        float4 v = in4[(size_t)s * D4 + c4];
        if (BIAS) {
            v.x = fmaxf(v.x + b.x, 0.f);
            v.y = fmaxf(v.y + b.y, 0.f);
            v.z = fmaxf(v.z + b.z, 0.f);
            v.w = fmaxf(v.w + b.w, 0.f);
        }
        acc.x = fmaf(v.x, w, acc.x);
        acc.y = fmaf(v.y, w, acc.y);
        acc.z = fmaf(v.z, w, acc.z);
        acc.w = fmaf(v.w, w, acc.w);
    }
    out4[(size_t)n * D4 + c4] = acc;
}

// ---------------- CSR gather aggregation (fp32 in, half out) ----------------
struct alignas(8) h4 { __half2 a, b; };
template <int D4>
__global__ void gather_agg_h_kernel(int inW, int N) {
    int t = blockIdx.x * blockDim.x + threadIdx.x;
    int n = t / D4, c4 = t % D4;
    if (n >= N) return;
    const float4* in4 = (const float4*)selbuf(inW);

    float4 acc = in4[(size_t)n * D4 + c4];
    float sn = g_self[n];
    acc.x *= sn; acc.y *= sn; acc.z *= sn; acc.w *= sn;

    int p0 = g_rowptr[n], p1 = g_rowptr[n + 1];
    for (int p = p0; p < p1; p++) {
        int   s = g_esrc[p];
        float w = g_ew[p];
        float4 v = in4[(size_t)s * D4 + c4];
        acc.x = fmaf(v.x, w, acc.x);
        acc.y = fmaf(v.y, w, acc.y);
        acc.z = fmaf(v.z, w, acc.z);
        acc.w = fmaf(v.w, w, acc.w);
    }
    h4 o;
    o.a = __float22half2_rn(make_float2(acc.x, acc.y));
    o.b = __float22half2_rn(make_float2(acc.z, acc.w));
    ((h4*)g_bufH)[(size_t)n * D4 + c4] = o;
}

// ---------------- CSR gather aggregation (half in, half out) ----------------
// Reads x4 as half from g_bufH2 (L2-resident 25.6MB) -> halves edge traffic.
template <int D4>
__global__ void gather_agg_hh_kernel(int N) {
    int t = blockIdx.x * blockDim.x + threadIdx.x;
    int n = t / D4, c4 = t % D4;
    if (n >= N) return;
    const h4* in4 = (const h4*)g_bufH2;

    h4 raw = in4[(size_t)n * D4 + c4];
    float2 l0 = __half22float2(raw.a), l1 = __half22float2(raw.b);
    float sn = g_self[n];
    float4 acc = make_float4(l0.x * sn, l0.y * sn, l1.x * sn, l1.y * sn);

    int p0 = g_rowptr[n], p1 = g_rowptr[n + 1];
    for (int p = p0; p < p1; p++) {
        int   s = g_esrc[p];
        float w = g_ew[p];
        h4 rv = in4[(size_t)s * D4 + c4];
        float2 v0 = __half22float2(rv.a), v1 = __half22float2(rv.b);
        acc.x = fmaf(v0.x, w, acc.x);
        acc.y = fmaf(v0.y, w, acc.y);
        acc.z = fmaf(v1.x, w, acc.z);
        acc.w = fmaf(v1.y, w, acc.w);
    }
    h4 o;
    o.a = __float22half2_rn(make_float2(acc.x, acc.y));
    o.b = __float22half2_rn(make_float2(acc.z, acc.w));
    ((h4*)g_bufH)[(size_t)n * D4 + c4] = o;
}

// ---------------- small matmul ----------------
template <int K, int OUT>
__global__ void mm_small_kernel(int inW, int outW,
                                const float* __restrict__ W,
                                const float* __restrict__ bias, int N) {
    __shared__ float Ws[K * OUT];
    __shared__ float bs[OUT];
    for (int i = threadIdx.x; i < K * OUT; i += blockDim.x) Ws[i] = W[i];
    for (int i = threadIdx.x; i < OUT; i += blockDim.x) bs[i] = bias[i];
    __syncthreads();
    const float* A = selbuf(inW);
    float*       C = selbuf(outW);
    int t = blockIdx.x * blockDim.x + threadIdx.x;
    int n = t / OUT, c = t % OUT;
    if (n >= N) return;
    const float* ar = A + (size_t)n * K;
    float acc = 0.0f;
#pragma unroll
    for (int k = 0; k < K; k++) acc = fmaf(ar[k], Ws[k * OUT + c], acc);
    C[(size_t)n * OUT + c] = fmaxf(acc + bs[c], 0.0f);
}

// ---------------- fp16 m16n8k16 GEMM with cp.async 4-stage pipeline ----------
// C = relu(Ah@W + b); OUTH=1 writes half to g_bufH2, else fp32 to selbuf(outW).
#define HSTAGES 4
#define H_PITCH 24
#define H_STG (128 * H_PITCH)                     // halves per tile stage
#define HGEMM_SMEM (HSTAGES * 2 * H_STG * 2)      // 49152 bytes

template <int OUTH>
__global__ __launch_bounds__(256, 2)
void hgemm_kernel(int outW, int wsel,
                  const float* __restrict__ bias,
                  int N, int K, int OUT) {
    extern __shared__ __half smh[];
    const uint32_t sbase = smem_u32(smh);

    const __half* Ah = g_bufH;
    const __half* Wt = (wsel == 4) ? g_w4h : g_w5h;
    float*        C  = selbuf(outW);

    const int tid    = threadIdx.x;
    const int lane   = tid & 31;
    const int warpId = tid >> 5;
    const int warpM  = warpId & 1;
    const int warpN  = warpId >> 1;
    const int gid    = lane >> 2;
    const int tig    = lane & 3;
    const int block_row = blockIdx.x * 128;
    const int block_col = blockIdx.y * 128;

    float c[4][4][4];
#pragma unroll
    for (int i = 0; i < 4; i++)
#pragma unroll
        for (int j = 0; j < 4; j++)
#pragma unroll
            for (int r = 0; r < 4; r++) c[i][j][r] = 0.0f;

    auto load_stage = [&](int st, int k0) {
#pragma unroll
        for (int it = 0; it < 2; it++) {
            int chunk = tid + it * 256;              // 0..511
            if (chunk < 256) {
                int r = chunk >> 1, c8 = (chunk & 1) * 8;
                int grow = block_row + r;
                const __half* src = &Ah[(size_t)grow * K + k0 + c8];
                uint32_t dst = sbase + (st * H_STG + r * H_PITCH + c8) * 2;
                uint32_t pred = (grow < N) ? 1u : 0u;
                asm volatile(
                    "{ .reg .pred p; setp.ne.u32 p, %2, 0;\n\t"
                    "@p cp.async.cg.shared.global [%0], [%1], 16; }"
                    :: "r"(dst), "l"(src), "r"(pred) : "memory");
            } else {
                int c2 = chunk - 256;
                int r = c2 >> 1, c8 = (c2 & 1) * 8;
                const __half* src = &Wt[(size_t)(block_col + r) * K + k0 + c8];
                uint32_t dst = sbase + (HSTAGES * H_STG + st * H_STG + r * H_PITCH + c8) * 2;
                asm volatile("cp.async.cg.shared.global [%0], [%1], 16;"
                             :: "r"(dst), "l"(src) : "memory");
            }
        }
    };

    const int ntiles = K >> 4;
    const int pre = (ntiles < 3) ? ntiles : 3;
    for (int st = 0; st < pre; st++) {
        load_stage(st, st * 16);
        asm volatile("cp.async.commit_group;" ::: "memory");
    }

    for (int ti = 0; ti < ntiles; ti++) {
        asm volatile("cp.async.wait_group 2;" ::: "memory");
        __syncthreads();
        int nxt = ti + 3;
        if (nxt < ntiles) load_stage(nxt & 3, nxt * 16);
        asm volatile("cp.async.commit_group;" ::: "memory");

        const int st = ti & 3;
        const __half* As = &smh[st * H_STG];
        const __half* Bs = &smh[HSTAGES * H_STG + st * H_STG];

        unsigned a[4][4], b[4][2];
#pragma unroll
        for (int mt = 0; mt < 4; mt++) {
            int mb = warpM * 64 + mt * 16;
            a[mt][0] = *(const unsigned*)&As[(mb + gid) * H_PITCH + 2 * tig];
            a[mt][1] = *(const unsigned*)&As[(mb + gid + 8) * H_PITCH + 2 * tig];
            a[mt][2] = *(const unsigned*)&As[(mb + gid) * H_PITCH + 2 * tig + 8];
            a[mt][3] = *(const unsigned*)&As[(mb + gid + 8) * H_PITCH + 2 * tig + 8];
        }
#pragma unroll
        for (int nt = 0; nt < 4; nt++) {
            int nb = warpN * 32 + nt * 8;
            b[nt][0] = *(const unsigned*)&Bs[(nb + gid) * H_PITCH + 2 * tig];
            b[nt][1] = *(const unsigned*)&Bs[(nb + gid) * H_PITCH + 2 * tig + 8];
        }
#pragma unroll
        for (int mt = 0; mt < 4; mt++)
#pragma unroll
            for (int nt = 0; nt < 4; nt++) {
                asm volatile(
                    "mma.sync.aligned.m16n8k16.row.col.f32.f16.f16.f32 "
                    "{%0,%1,%2,%3}, {%4,%5,%6,%7}, {%8,%9}, {%0,%1,%2,%3};"
                    : "+f"(c[mt][nt][0]), "+f"(c[mt][nt][1]),
                      "+f"(c[mt][nt][2]), "+f"(c[mt][nt][3])
                    : "r"(a[mt][0]), "r"(a[mt][1]), "r"(a[mt][2]), "r"(a[mt][3]),
                      "r"(b[nt][0]), "r"(b[nt][1]));
            }
    }

    // Epilogue
#pragma unroll
    for (int mt = 0; mt < 4; mt++) {
        int row0 = block_row + warpM * 64 + mt * 16 + gid;
#pragma unroll
        for (int nt = 0; nt < 4; nt++) {
            int col = block_col + warpN * 32 + nt * 8 + tig * 2;
            float bx = bias[col], by = bias[col + 1];
            float v0x = fmaxf(c[mt][nt][0] + bx, 0.f);
            float v0y = fmaxf(c[mt][nt][1] + by, 0.f);
            float v1x = fmaxf(c[mt][nt][2] + bx, 0.f);
            float v1y = fmaxf(c[mt][nt][3] + by, 0.f);
            if (OUTH) {
                if (row0 < N)
                    *(__half2*)&g_bufH2[(size_t)row0 * OUT + col] =
                        __float22half2_rn(make_float2(v0x, v0y));
                if (row0 + 8 < N)
                    *(__half2*)&g_bufH2[(size_t)(row0 + 8) * OUT + col] =
                        __float22half2_rn(make_float2(v1x, v1y));
            } else {
                if (row0 < N) {
                    float2 o; o.x = v0x; o.y = v0y;
                    *(float2*)&C[(size_t)row0 * OUT + col] = o;
                }
                if (row0 + 8 < N) {
                    float2 o; o.x = v1x; o.y = v1y;
                    *(float2*)&C[(size_t)(row0 + 8) * OUT + col] = o;
                }
            }
        }
    }
}

// ---------------- mean pool over sorted batch ids ----------------
__device__ __forceinline__ int lower_bound_idx(const void* a, int n, int v) {
    int lo = 0, hi = n;
    while (lo < hi) {
        int m = (lo + hi) >> 1;
        if (ld_idx(a, m) < v) lo = m + 1; else hi = m;
    }
    return lo;
}

__global__ void pool_kernel(int inW,
                            const void* __restrict__ batch,
                            float* __restrict__ out, int N, int B) {
    const float* x = selbuf(inW);
    int b = blockIdx.x;
    int cbase = blockIdx.y * 128;
    __shared__ int s_lo, s_hi;
    if (threadIdx.x == 0) {
        s_lo = lower_bound_idx(batch, N, b);
        s_hi = lower_bound_idx(batch, N, b + 1);
    }
    __syncthreads();
    int lo = s_lo, hi = s_hi;
    float inv = 1.0f / fmaxf((float)(hi - lo), 1.0f);
    int c = cbase + threadIdx.x;
    float s0 = 0.f, s1 = 0.f, s2 = 0.f, s3 = 0.f;
    int n = lo;
    for (; n + 3 < hi; n += 4) {
        s0 += x[(size_t)n * 512 + c];
        s1 += x[(size_t)(n + 1) * 512 + c];
        s2 += x[(size_t)(n + 2) * 512 + c];
        s3 += x[(size_t)(n + 3) * 512 + c];
    }
    for (; n < hi; n++) s0 += x[(size_t)n * 512 + c];
    out[(size_t)b * 512 + c] = (s0 + s1 + s2 + s3) * inv;
}

// ---------------- launch ----------------
static inline unsigned gr(long long n, int b) { return (unsigned)((n + b - 1) / b); }

extern "C" void kernel_launch(void* const* d_in, const int* in_sizes, int n_in,
                              void* d_out, int out_size) {
    const float* x     = (const float*)d_in[0];
    const void*  ei    = d_in[1];
    const void*  batch = d_in[2];
    const float *W1 = (const float*)d_in[3],  *b1 = (const float*)d_in[4];
    const float *W2 = (const float*)d_in[5],  *b2 = (const float*)d_in[6];
    const float *W3 = (const float*)d_in[7],  *b3 = (const float*)d_in[8];
    const float *W4 = (const float*)d_in[9],  *b4 = (const float*)d_in[10];
    const float *W5 = (const float*)d_in[11], *b5 = (const float*)d_in[12];

    const int N = in_sizes[0] / 32;
    const int E = in_sizes[1] / 2;
    const int B = out_size / 512;

    const int TB = 256;
    const int A = 0, Bb = 1;
    const int nb = (N + 1023) / 1024;

    static int smem_set = 0;
    if (!smem_set) {
        cudaFuncSetAttribute(hgemm_kernel<0>, cudaFuncAttributeMaxDynamicSharedMemorySize, HGEMM_SMEM);
        cudaFuncSetAttribute(hgemm_kernel<1>, cudaFuncAttributeMaxDynamicSharedMemorySize, HGEMM_SMEM);
        smem_set = 1;
    }

    __half *w4h, *w5h;
    cudaGetSymbolAddress((void**)&w4h, g_w4h);
    cudaGetSymbolAddress((void**)&w5h, g_w5h);

    // index dtype detection + CSR build + norms + weight transpose/convert
    detect_kernel<<<1, 32>>>((const int*)ei);
    zero_degi_kernel<<<gr(N, TB), TB>>>(N);
    deg_accum_kernel<<<gr(E, TB), TB>>>(ei, E);
    scan_phase1<<<nb, 1024>>>(N);
    scan_phase2<<<1, 64>>>(nb);
    scan_phase3<<<nb, 1024>>>(N);
    fill_kernel<<<gr(E, TB), TB>>>(ei, E);
    {
        dim3 t(32, 8);
        trconv_w_kernel<<<dim3(256 / 32, 64 / 32), t>>>(W4, w4h, 64, 256);
        trconv_w_kernel<<<dim3(512 / 32, 256 / 32), t>>>(W5, w5h, 256, 512);
    }

    // Layer 1 (32 -> 8)
    mm1_kernel<<<gr((long long)N * 8, TB), TB>>>(x, W1, N);
    gather_agg_kernel<2, 0><<<gr((long long)N * 2, TB), TB>>>(A, Bb, nullptr, N);

    // Layer 2 (8 -> 16)
    gather_agg_kernel<2, 1><<<gr((long long)N * 2, TB), TB>>>(Bb, A, b1, N);
    mm_small_kernel<8, 16><<<gr((long long)N * 16, TB), TB>>>(A, Bb, W2, b2, N);

    // Layer 3 (16 -> 64)
    gather_agg_kernel<4, 0><<<gr((long long)N * 4, TB), TB>>>(Bb, A, nullptr, N);
    mm_small_kernel<16, 64><<<gr((long long)N * 64, TB), TB>>>(A, Bb, W3, b3, N);

    // Layer 4 (64 -> 256): aggregate fp32->half, fp16 GEMM -> half x4 (g_bufH2).
    gather_agg_h_kernel<16><<<gr((long long)N * 16, TB), TB>>>(Bb, N);
    {
        dim3 grid(gr(N, 128), 256 / 128);
        hgemm_kernel<1><<<grid, 256, HGEMM_SMEM>>>(Bb, 4, b4, N, 64, 256);
    }

    // Layer 5 (256 -> 512): aggregate half->half, fp16 GEMM -> fp32 x5.
    gather_agg_hh_kernel<64><<<gr((long long)N * 64, TB), TB>>>(N);
    {
        dim3 grid(gr(N, 128), 512 / 128);
        hgemm_kernel<0><<<grid, 256, HGEMM_SMEM>>>(Bb, 5, b5, N, 256, 512);
    }

    // Global mean pool
    dim3 pgrid(B, 4);
    pool_kernel<<<pgrid, 128>>>(Bb, batch, (float*)d_out, N, B);
}

// round 13
// speedup vs baseline: 2.5713x; 1.1275x over previous
#include <cuda_runtime.h>
#include <cuda_fp16.h>
#include <math.h>
#include <stdint.h>

// Problem constants (match reference_code)
#define NN 50000
#define EE 400000
#define BB 50

// ---------------- scratch (static device allocations: allowed) ----------------
__device__ __align__(16) float  g_bufA[(size_t)NN * 64];
__device__ __align__(16) float  g_bufB[(size_t)NN * 64];
__device__ __align__(16) __half g_bufH[(size_t)NN * 256];   // gather out (GEMM in)
__device__ __align__(16) __half g_bufH2[(size_t)NN * 256];  // x4 (L4 GEMM out, half)
__device__ __align__(16) __half g_bufH5[(size_t)NN * 512];  // x5 (L5 GEMM out, half)
__device__ __align__(16) float  g_dinv[NN];
__device__ __align__(16) float  g_self[NN];
__device__ __align__(16) float  g_ew[EE];
__device__ __align__(16) __half g_w4h[256 * 64];    // W4^T half [256][64]
__device__ __align__(16) __half g_w5h[512 * 256];   // W5^T half [512][256]
__device__ int   g_degi[NN];
__device__ int   g_rowptr[NN + 1];
__device__ int   g_cursor[NN];
__device__ int   g_esrc[EE];
__device__ int   g_bsum[64];
__device__ int   g_is64;

__device__ __forceinline__ float* selbuf(int w) { return (w == 0) ? g_bufA : g_bufB; }

__device__ __forceinline__ int ld_idx(const void* p, long long i) {
    if (g_is64) return (int)((const long long*)p)[i];
    return ((const int*)p)[i];
}

__device__ __forceinline__ uint32_t smem_u32(const void* p) {
    uint32_t a;
    asm("{ .reg .u64 t; cvta.to.shared.u64 t, %1; cvt.u32.u64 %0, t; }" : "=r"(a) : "l"(p));
    return a;
}

// ---------------- zero + dtype detection (fused) ----------------
__global__ void zero_detect_kernel(const int* __restrict__ ei32, int N) {
    int t = blockIdx.x * blockDim.x + threadIdx.x;
    if (t < N) g_degi[t] = 0;
    if (t == 0) {
        int all0 = 1;
        for (int i = 1; i < 4096; i += 2) {
            if (ei32[i] != 0) { all0 = 0; break; }
        }
        g_is64 = all0;
    }
}

__global__ void deg_accum_kernel(const void* __restrict__ ei, int E) {
    int t = blockIdx.x * blockDim.x + threadIdx.x;
    if (t < E) atomicAdd(&g_degi[ld_idx(ei, (long long)E + t)], 1);
}

__global__ void scan_phase1(int N) {
    __shared__ int warp_tot[32];
    int i    = blockIdx.x * 1024 + threadIdx.x;
    int lane = threadIdx.x & 31, wid = threadIdx.x >> 5;
    int v = (i < N) ? g_degi[i] : 0;
    int incl = v;
#pragma unroll
    for (int off = 1; off < 32; off <<= 1) {
        int u = __shfl_up_sync(0xffffffffu, incl, off);
        if (lane >= off) incl += u;
    }
    if (lane == 31) warp_tot[wid] = incl;
    __syncthreads();
    if (wid == 0) {
        int w = warp_tot[lane];
#pragma unroll
        for (int off = 1; off < 32; off <<= 1) {
            int u = __shfl_up_sync(0xffffffffu, w, off);
            if (lane >= off) w += u;
        }
        warp_tot[lane] = w;
    }
    __syncthreads();
    if (wid > 0) incl += warp_tot[wid - 1];
    if (i < N) g_rowptr[i] = incl;
    if (threadIdx.x == 1023) g_bsum[blockIdx.x] = incl;
}

// phase2 (block-offset) folded in: warp 0 computes sum of bsum[0..bid-1].
__global__ void scan_phase3(int N) {
    __shared__ int s_off;
    int bid = blockIdx.x;
    if (threadIdx.x < 32) {
        int lane = threadIdx.x;
        int v = 0;
        if (lane < bid) v += g_bsum[lane];
        if (lane + 32 < bid) v += g_bsum[lane + 32];
#pragma unroll
        for (int off = 16; off > 0; off >>= 1)
            v += __shfl_down_sync(0xffffffffu, v, off);
        if (lane == 0) s_off = v;
    }
    __syncthreads();
    int i = bid * 1024 + threadIdx.x;
    if (i >= N) return;
    int v    = g_degi[i];
    int incl = g_rowptr[i] + s_off;
    int excl = incl - v;
    g_rowptr[i] = excl;
    g_cursor[i] = excl;
    float d  = (float)v + 1.0f;
    float di = rsqrtf(d);
    g_dinv[i] = di;
    g_self[i] = di * di;
    if (i == N - 1) g_rowptr[N] = incl;
}

__global__ void fill_kernel(const void* __restrict__ ei, int E) {
    int e = blockIdx.x * blockDim.x + threadIdx.x;
    if (e >= E) return;
    int s = ld_idx(ei, e);
    int d = ld_idx(ei, (long long)E + e);
    int p = atomicAdd(&g_cursor[d], 1);
    g_esrc[p] = s;
    g_ew[p]   = g_dinv[s] * g_dinv[d];
}

// ---------------- both W transposes in one launch (z selects) ----------------
__global__ void trconv_both_kernel(const float* __restrict__ W4,
                                   const float* __restrict__ W5) {
    __shared__ float tile[32][33];
    const float* in = (blockIdx.z == 0) ? W4 : W5;
    __half* out = (blockIdx.z == 0) ? g_w4h : g_w5h;
    int R  = (blockIdx.z == 0) ? 64 : 256;
    int Cc = (blockIdx.z == 0) ? 256 : 512;
    int c0 = blockIdx.x * 32, r0 = blockIdx.y * 32;
    if (c0 >= Cc || r0 >= R) return;
    int tx = threadIdx.x;
    for (int i = threadIdx.y; i < 32; i += 8) {
        int r = r0 + i, c = c0 + tx;
        tile[i][tx] = (r < R && c < Cc) ? in[(size_t)r * Cc + c] : 0.f;
    }
    __syncthreads();
    for (int i = threadIdx.y; i < 32; i += 8) {
        int orow = c0 + i, oc = r0 + tx;
        if (orow < Cc && oc < R) out[(size_t)orow * R + oc] = __float2half_rn(tile[tx][i]);
    }
}

// ---------------- layer 1 matmul (32 -> 8) ----------------
__global__ void mm1_kernel(const float* __restrict__ x,
                           const float* __restrict__ W, int N) {
    __shared__ float Ws[32 * 8];
    for (int i = threadIdx.x; i < 32 * 8; i += blockDim.x) Ws[i] = W[i];
    __syncthreads();
    int t = blockIdx.x * blockDim.x + threadIdx.x;
    int n = t >> 3, c = t & 7;
    if (n >= N) return;
    float acc = 0.0f;
    const float* xr = x + (size_t)n * 32;
#pragma unroll
    for (int k = 0; k < 32; k++) acc = fmaf(xr[k], Ws[k * 8 + c], acc);
    g_bufA[(size_t)n * 8 + c] = acc;
}

// ---------------- plain CSR gather (fp32), for L1 ----------------
template <int D4, int BIAS>
__global__ void gather_agg_kernel(int inW, int outW,
                                  const float* __restrict__ bias, int N) {
    int t = blockIdx.x * blockDim.x + threadIdx.x;
    int n = t / D4, c4 = t % D4;
    if (n >= N) return;
    const float4* in4  = (const float4*)selbuf(inW);
    float4*       out4 = (float4*)selbuf(outW);

    float4 b = make_float4(0.f, 0.f, 0.f, 0.f);
    if (BIAS) b = ((const float4*)bias)[c4];

    float4 acc = in4[(size_t)n * D4 + c4];
    if (BIAS) {
        acc.x = fmaxf(acc.x + b.x, 0.f);
        acc.y = fmaxf(acc.y + b.y, 0.f);
        acc.z = fmaxf(acc.z + b.z, 0.f);
        acc.w = fmaxf(acc.w + b.w, 0.f);
    }
    float sn = g_self[n];
    acc.x *= sn; acc.y *= sn; acc.z *= sn; acc.w *= sn;

    int p0 = g_rowptr[n], p1 = g_rowptr[n + 1];
    for (int p = p0; p < p1; p++) {
        int   s = g_esrc[p];
        float w = g_ew[p];
        float4 v = in4[(size_t)s * D4 + c4];
        if (BIAS) {
            v.x = fmaxf(v.x + b.x, 0.f);
            v.y = fmaxf(v.y + b.y, 0.f);
            v.z = fmaxf(v.z + b.z, 0.f);
            v.w = fmaxf(v.w + b.w, 0.f);
        }
        acc.x = fmaf(v.x, w, acc.x);
        acc.y = fmaf(v.y, w, acc.y);
        acc.z = fmaf(v.z, w, acc.z);
        acc.w = fmaf(v.w, w, acc.w);
    }
    out4[(size_t)n * D4 + c4] = acc;
}

// ---------------- fused gather (dim K) + matmul K->OUT + bias2+relu ----------
// NPB nodes per block, D4 = K/4 gather groups per node, THR = NPB*D4 threads.
// Phase 1: gather relu(in+b1)-weighted agg into smem [NPB][K].
// Phase 2: out[n][c] = relu(agg[n] @ W + b2).  OCPT = OUT*NPB/THR cols/thread.
template <int K, int OUT, int NPB, int BIAS1>
__global__ void fused_gather_mm_kernel(int inW, int outW,
                                       const float* __restrict__ b1,
                                       const float* __restrict__ W,
                                       const float* __restrict__ b2, int N) {
    constexpr int D4  = K / 4;
    constexpr int THR = NPB * D4;
    __shared__ float agg[NPB][K];
    __shared__ float Ws[K * OUT];
    __shared__ float bs[OUT];

    const float4* in4 = (const float4*)selbuf(inW);
    float*        C   = selbuf(outW);
    const int tid = threadIdx.x;
    const int nb0 = blockIdx.x * NPB;

    for (int i = tid; i < K * OUT; i += THR) Ws[i] = W[i];
    for (int i = tid; i < OUT; i += THR) bs[i] = b2[i];

    // phase 1: gather
    {
        int nl = tid / D4, c4 = tid % D4;
        int n  = nb0 + nl;
        if (n < N) {
            float4 b = make_float4(0.f, 0.f, 0.f, 0.f);
            if (BIAS1) b = ((const float4*)b1)[c4];
            float4 acc = in4[(size_t)n * D4 + c4];
            if (BIAS1) {
                acc.x = fmaxf(acc.x + b.x, 0.f);
                acc.y = fmaxf(acc.y + b.y, 0.f);
                acc.z = fmaxf(acc.z + b.z, 0.f);
                acc.w = fmaxf(acc.w + b.w, 0.f);
            }
            float sn = g_self[n];
            acc.x *= sn; acc.y *= sn; acc.z *= sn; acc.w *= sn;
            int p0 = g_rowptr[n], p1 = g_rowptr[n + 1];
            for (int p = p0; p < p1; p++) {
                int   s = g_esrc[p];
                float w = g_ew[p];
                float4 v = in4[(size_t)s * D4 + c4];
                if (BIAS1) {
                    v.x = fmaxf(v.x + b.x, 0.f);
                    v.y = fmaxf(v.y + b.y, 0.f);
                    v.z = fmaxf(v.z + b.z, 0.f);
                    v.w = fmaxf(v.w + b.w, 0.f);
                }
                acc.x = fmaf(v.x, w, acc.x);
                acc.y = fmaf(v.y, w, acc.y);
                acc.z = fmaf(v.z, w, acc.z);
                acc.w = fmaf(v.w, w, acc.w);
            }
            *(float4*)&agg[nl][c4 * 4] = acc;
        }
    }
    __syncthreads();

    // phase 2: matmul from smem
    {
        constexpr int CPT = OUT * NPB / THR;     // cols per thread
        constexpr int TPN = OUT / CPT;           // threads per node
        int nl = tid / TPN, cb = (tid % TPN) * CPT;
        int n  = nb0 + nl;
        if (n >= N) return;
        float acc[CPT];
#pragma unroll
        for (int j = 0; j < CPT; j++) acc[j] = bs[cb + j];
#pragma unroll
        for (int k = 0; k < K; k++) {
            float a = agg[nl][k];
#pragma unroll
            for (int j = 0; j < CPT; j++)
                acc[j] = fmaf(a, Ws[k * OUT + cb + j], acc[j]);
        }
#pragma unroll
        for (int j = 0; j < CPT; j += 4) {
            float4 o;
            o.x = fmaxf(acc[j + 0], 0.f);
            o.y = fmaxf(acc[j + 1], 0.f);
            o.z = fmaxf(acc[j + 2], 0.f);
            o.w = fmaxf(acc[j + 3], 0.f);
            *(float4*)&C[(size_t)n * OUT + cb + j] = o;
        }
    }
}

// ---------------- CSR gather (fp32 in dim 64, half out) for L4 --------------
struct alignas(8) h4 { __half2 a, b; };
template <int D4>
__global__ void gather_agg_h_kernel(int inW, int N) {
    int t = blockIdx.x * blockDim.x + threadIdx.x;
    int n = t / D4, c4 = t % D4;
    if (n >= N) return;
    const float4* in4 = (const float4*)selbuf(inW);

    float4 acc = in4[(size_t)n * D4 + c4];
    float sn = g_self[n];
    acc.x *= sn; acc.y *= sn; acc.z *= sn; acc.w *= sn;

    int p0 = g_rowptr[n], p1 = g_rowptr[n + 1];
    for (int p = p0; p < p1; p++) {
        int   s = g_esrc[p];
        float w = g_ew[p];
        float4 v = in4[(size_t)s * D4 + c4];
        acc.x = fmaf(v.x, w, acc.x);
        acc.y = fmaf(v.y, w, acc.y);
        acc.z = fmaf(v.z, w, acc.z);
        acc.w = fmaf(v.w, w, acc.w);
    }
    h4 o;
    o.a = __float22half2_rn(make_float2(acc.x, acc.y));
    o.b = __float22half2_rn(make_float2(acc.z, acc.w));
    ((h4*)g_bufH)[(size_t)n * D4 + c4] = o;
}

// ---------------- CSR gather (half in x4, half out) for L5 ------------------
template <int D4>
__global__ void gather_agg_hh_kernel(int N) {
    int t = blockIdx.x * blockDim.x + threadIdx.x;
    int n = t / D4, c4 = t % D4;
    if (n >= N) return;
    const h4* in4 = (const h4*)g_bufH2;

    h4 raw = in4[(size_t)n * D4 + c4];
    float2 l0 = __half22float2(raw.a), l1 = __half22float2(raw.b);
    float sn = g_self[n];
    float4 acc = make_float4(l0.x * sn, l0.y * sn, l1.x * sn, l1.y * sn);

    int p0 = g_rowptr[n], p1 = g_rowptr[n + 1];
    for (int p = p0; p < p1; p++) {
        int   s = g_esrc[p];
        float w = g_ew[p];
        h4 rv = in4[(size_t)s * D4 + c4];
        float2 v0 = __half22float2(rv.a), v1 = __half22float2(rv.b);
        acc.x = fmaf(v0.x, w, acc.x);
        acc.y = fmaf(v0.y, w, acc.y);
        acc.z = fmaf(v1.x, w, acc.z);
        acc.w = fmaf(v1.y, w, acc.w);
    }
    h4 o;
    o.a = __float22half2_rn(make_float2(acc.x, acc.y));
    o.b = __float22half2_rn(make_float2(acc.z, acc.w));
    ((h4*)g_bufH)[(size_t)n * D4 + c4] = o;
}

// ---------------- fp16 m16n8k16 GEMM with cp.async 4-stage pipeline ----------
// OUTSEL: 1 -> half to g_bufH2 (x4), 2 -> half to g_bufH5 (x5).
#define HSTAGES 4
#define H_PITCH 24
#define H_STG (128 * H_PITCH)
#define HGEMM_SMEM (HSTAGES * 2 * H_STG * 2)

template <int OUTSEL>
__global__ __launch_bounds__(256, 2)
void hgemm_kernel(int wsel, const float* __restrict__ bias,
                  int N, int K, int OUT) {
    extern __shared__ __half smh[];
    const uint32_t sbase = smem_u32(smh);

    const __half* Ah = g_bufH;
    const __half* Wt = (wsel == 4) ? g_w4h : g_w5h;
    __half*       Ch = (OUTSEL == 1) ? g_bufH2 : g_bufH5;

    const int tid    = threadIdx.x;
    const int lane   = tid & 31;
    const int warpId = tid >> 5;
    const int warpM  = warpId & 1;
    const int warpN  = warpId >> 1;
    const int gid    = lane >> 2;
    const int tig    = lane & 3;
    const int block_row = blockIdx.x * 128;
    const int block_col = blockIdx.y * 128;

    float c[4][4][4];
#pragma unroll
    for (int i = 0; i < 4; i++)
#pragma unroll
        for (int j = 0; j < 4; j++)
#pragma unroll
            for (int r = 0; r < 4; r++) c[i][j][r] = 0.0f;

    auto load_stage = [&](int st, int k0) {
#pragma unroll
        for (int it = 0; it < 2; it++) {
            int chunk = tid + it * 256;
            if (chunk < 256) {
                int r = chunk >> 1, c8 = (chunk & 1) * 8;
                int grow = block_row + r;
                const __half* src = &Ah[(size_t)grow * K + k0 + c8];
                uint32_t dst = sbase + (st * H_STG + r * H_PITCH + c8) * 2;
                uint32_t pred = (grow < N) ? 1u : 0u;
                asm volatile(
                    "{ .reg .pred p; setp.ne.u32 p, %2, 0;\n\t"
                    "@p cp.async.cg.shared.global [%0], [%1], 16; }"
                    :: "r"(dst), "l"(src), "r"(pred) : "memory");
            } else {
                int c2 = chunk - 256;
                int r = c2 >> 1, c8 = (c2 & 1) * 8;
                const __half* src = &Wt[(size_t)(block_col + r) * K + k0 + c8];
                uint32_t dst = sbase + (HSTAGES * H_STG + st * H_STG + r * H_PITCH + c8) * 2;
                asm volatile("cp.async.cg.shared.global [%0], [%1], 16;"
                             :: "r"(dst), "l"(src) : "memory");
            }
        }
    };

    const int ntiles = K >> 4;
    const int pre = (ntiles < 3) ? ntiles : 3;
    for (int st = 0; st < pre; st++) {
        load_stage(st, st * 16);
        asm volatile("cp.async.commit_group;" ::: "memory");
    }

    for (int ti = 0; ti < ntiles; ti++) {
        asm volatile("cp.async.wait_group 2;" ::: "memory");
        __syncthreads();
        int nxt = ti + 3;
        if (nxt < ntiles) load_stage(nxt & 3, nxt * 16);
        asm volatile("cp.async.commit_group;" ::: "memory");

        const int st = ti & 3;
        const __half* As = &smh[st * H_STG];
        const __half* Bs = &smh[HSTAGES * H_STG + st * H_STG];

        unsigned a[4][4], b[4][2];
#pragma unroll
        for (int mt = 0; mt < 4; mt++) {
            int mb = warpM * 64 + mt * 16;
            a[mt][0] = *(const unsigned*)&As[(mb + gid) * H_PITCH + 2 * tig];
            a[mt][1] = *(const unsigned*)&As[(mb + gid + 8) * H_PITCH + 2 * tig];
            a[mt][2] = *(const unsigned*)&As[(mb + gid) * H_PITCH + 2 * tig + 8];
            a[mt][3] = *(const unsigned*)&As[(mb + gid + 8) * H_PITCH + 2 * tig + 8];
        }
#pragma unroll
        for (int nt = 0; nt < 4; nt++) {
            int nb = warpN * 32 + nt * 8;
            b[nt][0] = *(const unsigned*)&Bs[(nb + gid) * H_PITCH + 2 * tig];
            b[nt][1] = *(const unsigned*)&Bs[(nb + gid) * H_PITCH + 2 * tig + 8];
        }
#pragma unroll
        for (int mt = 0; mt < 4; mt++)
#pragma unroll
            for (int nt = 0; nt < 4; nt++) {
                asm volatile(
                    "mma.sync.aligned.m16n8k16.row.col.f32.f16.f16.f32 "
                    "{%0,%1,%2,%3}, {%4,%5,%6,%7}, {%8,%9}, {%0,%1,%2,%3};"
                    : "+f"(c[mt][nt][0]), "+f"(c[mt][nt][1]),
                      "+f"(c[mt][nt][2]), "+f"(c[mt][nt][3])
                    : "r"(a[mt][0]), "r"(a[mt][1]), "r"(a[mt][2]), "r"(a[mt][3]),
                      "r"(b[nt][0]), "r"(b[nt][1]));
            }
    }

    // Epilogue: bias + relu -> half
#pragma unroll
    for (int mt = 0; mt < 4; mt++) {
        int row0 = block_row + warpM * 64 + mt * 16 + gid;
#pragma unroll
        for (int nt = 0; nt < 4; nt++) {
            int col = block_col + warpN * 32 + nt * 8 + tig * 2;
            float bx = bias[col], by = bias[col + 1];
            float v0x = fmaxf(c[mt][nt][0] + bx, 0.f);
            float v0y = fmaxf(c[mt][nt][1] + by, 0.f);
            float v1x = fmaxf(c[mt][nt][2] + bx, 0.f);
            float v1y = fmaxf(c[mt][nt][3] + by, 0.f);
            if (row0 < N)
                *(__half2*)&Ch[(size_t)row0 * OUT + col] =
                    __float22half2_rn(make_float2(v0x, v0y));
            if (row0 + 8 < N)
                *(__half2*)&Ch[(size_t)(row0 + 8) * OUT + col] =
                    __float22half2_rn(make_float2(v1x, v1y));
        }
    }
}

// ---------------- mean pool over sorted batch ids (half x5 input) -----------
__device__ __forceinline__ int lower_bound_idx(const void* a, int n, int v) {
    int lo = 0, hi = n;
    while (lo < hi) {
        int m = (lo + hi) >> 1;
        if (ld_idx(a, m) < v) lo = m + 1; else hi = m;
    }
    return lo;
}

__global__ void pool_kernel(const void* __restrict__ batch,
                            float* __restrict__ out, int N, int B) {
    const __half* x = g_bufH5;
    int b = blockIdx.x;
    int cbase = blockIdx.y * 128;
    __shared__ int s_lo, s_hi;
    if (threadIdx.x == 0) {
        s_lo = lower_bound_idx(batch, N, b);
        s_hi = lower_bound_idx(batch, N, b + 1);
    }
    __syncthreads();
    int lo = s_lo, hi = s_hi;
    float inv = 1.0f / fmaxf((float)(hi - lo), 1.0f);
    int c = cbase + threadIdx.x;
    float s0 = 0.f, s1 = 0.f, s2 = 0.f, s3 = 0.f;
    int n = lo;
    for (; n + 3 < hi; n += 4) {
        s0 += __half2float(x[(size_t)n * 512 + c]);
        s1 += __half2float(x[(size_t)(n + 1) * 512 + c]);
        s2 += __half2float(x[(size_t)(n + 2) * 512 + c]);
        s3 += __half2float(x[(size_t)(n + 3) * 512 + c]);
    }
    for (; n < hi; n++) s0 += __half2float(x[(size_t)n * 512 + c]);
    out[(size_t)b * 512 + c] = (s0 + s1 + s2 + s3) * inv;
}

// ---------------- launch ----------------
static inline unsigned gr(long long n, int b) { return (unsigned)((n + b - 1) / b); }

extern "C" void kernel_launch(void* const* d_in, const int* in_sizes, int n_in,
                              void* d_out, int out_size) {
    const float* x     = (const float*)d_in[0];
    const void*  ei    = d_in[1];
    const void*  batch = d_in[2];
    const float *W1 = (const float*)d_in[3],  *b1 = (const float*)d_in[4];
    const float *W2 = (const float*)d_in[5],  *b2 = (const float*)d_in[6];
    const float *W3 = (const float*)d_in[7],  *b3 = (const float*)d_in[8];
    const float *W4 = (const float*)d_in[9],  *b4 = (const float*)d_in[10];
    const float *W5 = (const float*)d_in[11], *b5 = (const float*)d_in[12];

    const int N = in_sizes[0] / 32;
    const int E = in_sizes[1] / 2;
    const int B = out_size / 512;

    const int TB = 256;
    const int A = 0, Bb = 1;
    const int nb = (N + 1023) / 1024;

    static int smem_set = 0;
    if (!smem_set) {
        cudaFuncSetAttribute(hgemm_kernel<1>, cudaFuncAttributeMaxDynamicSharedMemorySize, HGEMM_SMEM);
        cudaFuncSetAttribute(hgemm_kernel<2>, cudaFuncAttributeMaxDynamicSharedMemorySize, HGEMM_SMEM);
        smem_set = 1;
    }

    // CSR build + norms + weight transpose/convert (5 launches + 1)
    zero_detect_kernel<<<gr(N, TB), TB>>>((const int*)ei, N);
    deg_accum_kernel<<<gr(E, TB), TB>>>(ei, E);
    scan_phase1<<<nb, 1024>>>(N);
    scan_phase3<<<nb, 1024>>>(N);
    fill_kernel<<<gr(E, TB), TB>>>(ei, E);
    trconv_both_kernel<<<dim3(16, 8, 2), dim3(32, 8)>>>(W4, W5);

    // Layer 1 (32 -> 8): mm1 -> bufA, gather -> bufB
    mm1_kernel<<<gr((long long)N * 8, TB), TB>>>(x, W1, N);
    gather_agg_kernel<2, 0><<<gr((long long)N * 2, TB), TB>>>(A, Bb, nullptr, N);

    // Layer 2 fused: gather relu(bufB+b1) (dim8) + mm 8->16 -> bufA
    fused_gather_mm_kernel<8, 16, 128, 1><<<gr(N, 128), 256>>>(Bb, A, b1, W2, b2, N);

    // Layer 3 fused: gather bufA (dim16) + mm 16->64 -> bufB
    fused_gather_mm_kernel<16, 64, 64, 0><<<gr(N, 64), 256>>>(A, Bb, nullptr, W3, b3, N);

    // Layer 4: gather bufB (dim64, fp32) -> half g_bufH; GEMM -> half x4.
    gather_agg_h_kernel<16><<<gr((long long)N * 16, TB), TB>>>(Bb, N);
    {
        dim3 grid(gr(N, 128), 256 / 128);
        hgemm_kernel<1><<<grid, 256, HGEMM_SMEM>>>(4, b4, N, 64, 256);
    }

    // Layer 5: gather x4 (half) -> half g_bufH; GEMM -> half x5.
    gather_agg_hh_kernel<64><<<gr((long long)N * 64, TB), TB>>>(N);
    {
        dim3 grid(gr(N, 128), 512 / 128);
        hgemm_kernel<2><<<grid, 256, HGEMM_SMEM>>>(5, b5, N, 256, 512);
    }

    // Global mean pool from half x5
    dim3 pgrid(B, 4);
    pool_kernel<<<pgrid, 128>>>(batch, (float*)d_out, N, B);
}